// round 1
// baseline (speedup 1.0000x reference)
#include <cuda_runtime.h>
#include <cstdint>

#define HW   16384
#define Hdim 128
#define Wdim 128

typedef unsigned long long u64;

__device__ __forceinline__ u64 pk2(float lo, float hi){
  u64 r; asm("mov.b64 %0, {%1, %2};" : "=l"(r) : "f"(lo), "f"(hi)); return r;
}
__device__ __forceinline__ void upk2(u64 v, float &lo, float &hi){
  asm("mov.b64 {%0, %1}, %2;" : "=f"(lo), "=f"(hi) : "l"(v));
}
__device__ __forceinline__ void fma2(u64 &d, u64 a, u64 b){
  asm("fma.rn.f32x2 %0, %1, %2, %0;" : "+l"(d) : "l"(a), "l"(b));
}

// Scratch (allocation-free rule: __device__ globals)
__device__ float g_h [16ULL*256*16384];   // pf output: a (ch 0..127) | xh (ch 128..255)
__device__ float g_t1[16ULL*64*16384];
__device__ float g_t2[16ULL*64*16384];
__device__ float g_x3[16ULL*64*16384];
__device__ float g_at[16ULL*128*16384];   // attn (concat of attn_1, attn_2)

// ---------------------------------------------------------------------------
// Pointwise (1x1) conv as GEMM over 128-pixel tiles. Optional fused:
//   LNORM: channel LayerNorm on the staged X tile (used by pf)
//   INMUL: X := in * in2 elementwise on load (used by pl: xh * attn)
//   EPI=0: out = acc + bias
//   EPI=1: out = (acc + bias) * aux          (gating multiply)
//   EPI=2: out = (acc + bias) * scale[oc] + shortcut   (final residual)
// ---------------------------------------------------------------------------
template<int CIN, int COUT, bool LNORM, bool INMUL, int EPI>
__global__ __launch_bounds__(256)
void pw_kernel(const float* __restrict__ in, long long in_bs,
               const float* __restrict__ in2, long long in2_bs,
               const float* __restrict__ lnw, const float* __restrict__ lnb,
               const float* __restrict__ w, const float* __restrict__ bias,
               const float* __restrict__ aux, long long aux_bs,
               const float* __restrict__ scal, const float* __restrict__ shortcut,
               float* __restrict__ out, long long out_bs)
{
  extern __shared__ float smem[];
  float* Xs = smem;                    // CIN * 128
  float* Ws = smem + CIN*128;          // 64 * (CIN+1)  (padded rows)
  const int b  = blockIdx.y;
  const int p0 = blockIdx.x * 128;
  const float* ip  = in + (long long)b*in_bs + p0;
  const float* ip2 = INMUL ? (in2 + (long long)b*in2_bs + p0) : nullptr;

  // stage X tile (float4 loads, coalesced)
  for (int i = threadIdx.x; i < CIN*32; i += 256){
    int ic = i >> 5;
    int p4 = (i & 31) << 2;
    float4 v = *(const float4*)(ip + (long long)ic*HW + p4);
    if (INMUL){
      float4 m = *(const float4*)(ip2 + (long long)ic*HW + p4);
      v.x *= m.x; v.y *= m.y; v.z *= m.z; v.w *= m.w;
    }
    *(float4*)(Xs + ic*128 + p4) = v;
  }

  if (LNORM){
    __syncthreads();
    if (threadIdx.x < 128){
      const int p = threadIdx.x;
      float s = 0.f, s2 = 0.f;
      #pragma unroll
      for (int ic = 0; ic < CIN; ic++){ float v = Xs[ic*128 + p]; s += v; s2 += v*v; }
      const float mu = s * (1.f/CIN);
      const float rs = rsqrtf(s2*(1.f/CIN) - mu*mu + 1e-6f);
      #pragma unroll
      for (int ic = 0; ic < CIN; ic++){
        float v = Xs[ic*128 + p];
        Xs[ic*128 + p] = __ldg(&lnw[ic]) * ((v - mu) * rs) + __ldg(&lnb[ic]);
      }
    }
  }

  const int px  = threadIdx.x & 15;          // pixel lane: pixels px + 16k, k=0..7
  const int toc = (threadIdx.x >> 4) << 2;   // 4 output channels per thread

  for (int occ = 0; occ < COUT; occ += 64){
    __syncthreads();
    for (int i = threadIdx.x; i < 64*CIN; i += 256){
      int o = i / CIN, ic = i % CIN;
      Ws[o*(CIN+1) + ic] = w[(occ + o)*CIN + ic];
    }
    __syncthreads();

    u64 acc[4][4];
    #pragma unroll
    for (int j = 0; j < 4; j++)
      #pragma unroll
      for (int k = 0; k < 4; k++) acc[j][k] = 0ULL;

    #pragma unroll 4
    for (int ic = 0; ic < CIN; ic++){
      const float* xr = Xs + ic*128 + px;
      u64 xp0 = pk2(xr[0],  xr[16]);
      u64 xp1 = pk2(xr[32], xr[48]);
      u64 xp2 = pk2(xr[64], xr[80]);
      u64 xp3 = pk2(xr[96], xr[112]);
      const float* wc = Ws + toc*(CIN+1) + ic;
      #pragma unroll
      for (int j = 0; j < 4; j++){
        float wv = wc[j*(CIN+1)];
        u64 wp = pk2(wv, wv);
        fma2(acc[j][0], wp, xp0);
        fma2(acc[j][1], wp, xp1);
        fma2(acc[j][2], wp, xp2);
        fma2(acc[j][3], wp, xp3);
      }
    }

    #pragma unroll
    for (int j = 0; j < 4; j++){
      const int oc = occ + toc + j;
      const float bz = bias[oc];
      float* op = out + (long long)b*out_bs + (long long)oc*HW + p0 + px;
      const float* ax  = (EPI==1) ? (aux + (long long)b*aux_bs + (long long)oc*HW + p0 + px) : nullptr;
      const float scv  = (EPI==2) ? scal[oc] : 0.f;
      const float* shp = (EPI==2) ? (shortcut + ((long long)b*COUT + oc)*HW + p0 + px) : nullptr;
      #pragma unroll
      for (int k = 0; k < 4; k++){
        float lo, hi; upk2(acc[j][k], lo, hi);
        float r0 = lo + bz, r1 = hi + bz;
        if (EPI==1){ r0 *= ax[32*k]; r1 *= ax[32*k + 16]; }
        if (EPI==2){ r0 = r0*scv + shp[32*k]; r1 = r1*scv + shp[32*k + 16]; }
        op[32*k] = r0; op[32*k + 16] = r1;
      }
    }
  }
}

// ---------------------------------------------------------------------------
// Depthwise conv, "same" padding (pad = DIL*(K-1)/2), 64 channels.
// 32x32 output tile in smem with halo; thread computes 4 consecutive-x outputs.
// ---------------------------------------------------------------------------
template<int KH, int KW, int DIL>
__global__ __launch_bounds__(256)
void dw_kernel(const float* __restrict__ in, long long in_bs,
               const float* __restrict__ w, const float* __restrict__ bias,
               float* __restrict__ out, long long out_bs)
{
  constexpr int RH   = DIL*(KH-1)/2, RW = DIL*(KW-1)/2;
  constexpr int SH   = 32 + 2*RH;
  constexpr int SW   = 32 + 2*RW;
  constexpr int SWP  = (SW & 1) ? SW : (SW + 1);   // odd stride: conflict-free lanes
  constexpr int SPAN = 4 + (KW-1)*DIL;
  __shared__ float sm[SH*SWP];

  const int bc = blockIdx.z;
  const int c  = bc & 63;
  const int b  = bc >> 6;
  const int ty0 = blockIdx.y * 32, tx0 = blockIdx.x * 32;
  const float* ip = in + (long long)b*in_bs + (long long)c*HW;

  for (int i = threadIdx.x; i < SH*SW; i += 256){
    int sy = i / SW, sx = i - sy*SW;
    int gy = ty0 + sy - RH, gx = tx0 + sx - RW;
    float v = 0.f;
    if ((unsigned)gy < 128u && (unsigned)gx < 128u) v = ip[gy*Wdim + gx];
    sm[sy*SWP + sx] = v;
  }
  float wr[KH*KW];
  #pragma unroll
  for (int i = 0; i < KH*KW; i++) wr[i] = __ldg(&w[c*KH*KW + i]);
  const float bz = __ldg(&bias[c]);
  __syncthreads();

  const int oy  = threadIdx.x >> 3;
  const int ox0 = (threadIdx.x & 7) << 2;
  float a0 = bz, a1 = bz, a2 = bz, a3 = bz;
  #pragma unroll
  for (int ky = 0; ky < KH; ky++){
    const float* row = sm + (oy + ky*DIL)*SWP + ox0;
    float buf[SPAN];
    #pragma unroll
    for (int i = 0; i < SPAN; i++) buf[i] = row[i];
    #pragma unroll
    for (int kx = 0; kx < KW; kx++){
      const float wv = wr[ky*KW + kx];
      a0 += wv * buf[kx*DIL + 0];
      a1 += wv * buf[kx*DIL + 1];
      a2 += wv * buf[kx*DIL + 2];
      a3 += wv * buf[kx*DIL + 3];
    }
  }
  float4 r = make_float4(a0, a1, a2, a3);
  *(float4*)(out + (long long)b*out_bs + (long long)c*HW
             + (long long)(ty0 + oy)*Wdim + tx0 + ox0) = r;
}

// ---------------------------------------------------------------------------
extern "C" void kernel_launch(void* const* d_in, const int* in_sizes, int n_in,
                              void* d_out, int out_size)
{
  const float* x    = (const float*)d_in[0];
  const float* ln_w = (const float*)d_in[1];
  const float* ln_b = (const float*)d_in[2];
  const float* scale= (const float*)d_in[3];
  const float* pf_w = (const float*)d_in[4];
  const float* pf_b = (const float*)d_in[5];
  const float* l3w1 = (const float*)d_in[6];
  const float* l3b1 = (const float*)d_in[7];
  const float* l3w2 = (const float*)d_in[8];
  const float* l3b2 = (const float*)d_in[9];
  const float* l3w3 = (const float*)d_in[10];
  const float* l3b3 = (const float*)d_in[11];
  const float* l3w4 = (const float*)d_in[12];
  const float* l3b4 = (const float*)d_in[13];
  const float* l5w1 = (const float*)d_in[14];
  const float* l5b1 = (const float*)d_in[15];
  const float* l5w2 = (const float*)d_in[16];
  const float* l5b2 = (const float*)d_in[17];
  const float* l5w3 = (const float*)d_in[18];
  const float* l5b3 = (const float*)d_in[19];
  const float* x3aw = (const float*)d_in[20];
  const float* x3ab = (const float*)d_in[21];
  const float* x3bw = (const float*)d_in[22];
  const float* x3bb = (const float*)d_in[23];
  const float* x5w  = (const float*)d_in[24];
  const float* x5b  = (const float*)d_in[25];
  const float* pl_w = (const float*)d_in[26];
  const float* pl_b = (const float*)d_in[27];
  float* out = (float*)d_out;

  float *p_h, *p_t1, *p_t2, *p_x3, *p_at;
  cudaGetSymbolAddress((void**)&p_h,  g_h);
  cudaGetSymbolAddress((void**)&p_t1, g_t1);
  cudaGetSymbolAddress((void**)&p_t2, g_t2);
  cudaGetSymbolAddress((void**)&p_x3, g_x3);
  cudaGetSymbolAddress((void**)&p_at, g_at);

  const long long BS_H = 256LL*HW, BS64 = 64LL*HW, BS128 = 128LL*HW;
  dim3 gpw(128, 16);
  dim3 gdw(4, 4, 16*64);

  // 1) LN + pf expand (128 -> 256)
  {
    auto k = pw_kernel<128,256,true,false,0>;
    size_t smb = (128*128 + 64*129) * sizeof(float);
    cudaFuncSetAttribute((const void*)k, cudaFuncAttributeMaxDynamicSharedMemorySize, (int)smb);
    k<<<gpw,256,smb>>>(x, BS128, nullptr,0, ln_w, ln_b, pf_w, pf_b,
                       nullptr,0, nullptr, nullptr, p_h, BS_H);
  }
  // 2) branch 1 (a1 = g_h ch 0..63)
  dw_kernel<1,3,1><<<gdw,256>>>(p_h,  BS_H, x3aw, x3ab, p_t1, BS64);
  dw_kernel<3,1,1><<<gdw,256>>>(p_t1, BS64, x3bw, x3bb, p_x3, BS64);   // x3_out
  dw_kernel<1,3,1><<<gdw,256>>>(p_h,  BS_H, l3w1, l3b1, p_t1, BS64);
  dw_kernel<3,1,1><<<gdw,256>>>(p_t1, BS64, l3w2, l3b2, p_t2, BS64);
  dw_kernel<5,5,2><<<gdw,256>>>(p_t2, BS64, l3w3, l3b3, p_t1, BS64);
  {
    auto k = pw_kernel<64,64,false,false,1>;                           // l3 pw * x3_out
    size_t smb = (64*128 + 64*65) * sizeof(float);
    cudaFuncSetAttribute((const void*)k, cudaFuncAttributeMaxDynamicSharedMemorySize, (int)smb);
    k<<<gpw,256,smb>>>(p_t1, BS64, nullptr,0, nullptr,nullptr, l3w4, l3b4,
                       p_x3, BS64, nullptr, nullptr, p_at, BS128);
  }
  // 3) branch 2 (a2 = g_h ch 64..127)
  dw_kernel<5,5,1><<<gdw,256>>>(p_h + 64LL*HW, BS_H, x5w,  x5b,  p_x3, BS64);  // x5 gate
  dw_kernel<5,5,1><<<gdw,256>>>(p_h + 64LL*HW, BS_H, l5w1, l5b1, p_t1, BS64);
  dw_kernel<7,7,2><<<gdw,256>>>(p_t1, BS64, l5w2, l5b2, p_t2, BS64);
  {
    auto k = pw_kernel<64,64,false,false,1>;                           // l5 pw * x5
    size_t smb = (64*128 + 64*65) * sizeof(float);
    k<<<gpw,256,smb>>>(p_t2, BS64, nullptr,0, nullptr,nullptr, l5w3, l5b3,
                       p_x3, BS64, nullptr, nullptr, p_at + 64LL*HW, BS128);
  }
  // 4) final: pl( xh * attn ) * scale + x
  {
    auto k = pw_kernel<128,128,false,true,2>;
    size_t smb = (128*128 + 64*129) * sizeof(float);
    cudaFuncSetAttribute((const void*)k, cudaFuncAttributeMaxDynamicSharedMemorySize, (int)smb);
    k<<<gpw,256,smb>>>(p_h + 128LL*HW, BS_H, p_at, BS128, nullptr, nullptr,
                       pl_w, pl_b, nullptr,0, scale, x, out, BS128);
  }
}

// round 2
// speedup vs baseline: 1.1365x; 1.1365x over previous
#include <cuda_runtime.h>
#include <cstdint>

#define HW   16384
#define Hdim 128
#define Wdim 128

typedef unsigned long long u64;

__device__ __forceinline__ u64 pk2(float lo, float hi){
  u64 r; asm("mov.b64 %0, {%1, %2};" : "=l"(r) : "f"(lo), "f"(hi)); return r;
}
__device__ __forceinline__ void upk2(u64 v, float &lo, float &hi){
  asm("mov.b64 {%0, %1}, %2;" : "=f"(lo), "=f"(hi) : "l"(v));
}
__device__ __forceinline__ void fma2(u64 &d, u64 a, u64 b){
  asm("fma.rn.f32x2 %0, %1, %2, %0;" : "+l"(d) : "l"(a), "l"(b));
}

// Scratch (allocation-free rule: __device__ globals)
__device__ float g_h [16ULL*256*16384];   // pf output: a (ch 0..127) | xh (ch 128..255)
__device__ float g_t1[16ULL*64*16384];    // l3pre
__device__ float g_t2[16ULL*64*16384];    // l5pre
__device__ float g_x3[16ULL*64*16384];    // x3_out, later reused for x5
__device__ float g_at[16ULL*128*16384];   // attn (concat of attn_1, attn_2)

// ---------------------------------------------------------------------------
// Pointwise (1x1) conv as GEMM over 128-pixel tiles (f32x2 FFMA). Fused:
//   LNORM: channel LayerNorm on the staged X tile (pf)
//   INMUL: X := in * in2 elementwise on load (pl: xh * attn)
//   EPI=0: out = acc + bias
//   EPI=1: out = (acc + bias) * aux
//   EPI=2: out = (acc + bias) * scale[oc] + shortcut
// ---------------------------------------------------------------------------
template<int CIN, int COUT, bool LNORM, bool INMUL, int EPI>
__global__ __launch_bounds__(256)
void pw_kernel(const float* __restrict__ in, long long in_bs,
               const float* __restrict__ in2, long long in2_bs,
               const float* __restrict__ lnw, const float* __restrict__ lnb,
               const float* __restrict__ w, const float* __restrict__ bias,
               const float* __restrict__ aux, long long aux_bs,
               const float* __restrict__ scal, const float* __restrict__ shortcut,
               float* __restrict__ out, long long out_bs)
{
  extern __shared__ float smem[];
  float* Xs = smem;                    // CIN * 128
  float* Ws = smem + CIN*128;          // 64 * (CIN+1)
  const int b  = blockIdx.y;
  const int p0 = blockIdx.x * 128;
  const float* ip  = in + (long long)b*in_bs + p0;
  const float* ip2 = INMUL ? (in2 + (long long)b*in2_bs + p0) : nullptr;

  for (int i = threadIdx.x; i < CIN*32; i += 256){
    int ic = i >> 5;
    int p4 = (i & 31) << 2;
    float4 v = *(const float4*)(ip + (long long)ic*HW + p4);
    if (INMUL){
      float4 m = *(const float4*)(ip2 + (long long)ic*HW + p4);
      v.x *= m.x; v.y *= m.y; v.z *= m.z; v.w *= m.w;
    }
    *(float4*)(Xs + ic*128 + p4) = v;
  }

  if (LNORM){
    __syncthreads();
    if (threadIdx.x < 128){
      const int p = threadIdx.x;
      float s = 0.f, s2 = 0.f;
      #pragma unroll
      for (int ic = 0; ic < CIN; ic++){ float v = Xs[ic*128 + p]; s += v; s2 += v*v; }
      const float mu = s * (1.f/CIN);
      const float rs = rsqrtf(s2*(1.f/CIN) - mu*mu + 1e-6f);
      #pragma unroll
      for (int ic = 0; ic < CIN; ic++){
        float v = Xs[ic*128 + p];
        Xs[ic*128 + p] = __ldg(&lnw[ic]) * ((v - mu) * rs) + __ldg(&lnb[ic]);
      }
    }
  }

  const int px  = threadIdx.x & 15;
  const int toc = (threadIdx.x >> 4) << 2;

  for (int occ = 0; occ < COUT; occ += 64){
    __syncthreads();
    for (int i = threadIdx.x; i < 64*CIN; i += 256){
      int o = i / CIN, ic = i % CIN;
      Ws[o*(CIN+1) + ic] = w[(occ + o)*CIN + ic];
    }
    __syncthreads();

    u64 acc[4][4];
    #pragma unroll
    for (int j = 0; j < 4; j++)
      #pragma unroll
      for (int k = 0; k < 4; k++) acc[j][k] = 0ULL;

    #pragma unroll 4
    for (int ic = 0; ic < CIN; ic++){
      const float* xr = Xs + ic*128 + px;
      u64 xp0 = pk2(xr[0],  xr[16]);
      u64 xp1 = pk2(xr[32], xr[48]);
      u64 xp2 = pk2(xr[64], xr[80]);
      u64 xp3 = pk2(xr[96], xr[112]);
      const float* wc = Ws + toc*(CIN+1) + ic;
      #pragma unroll
      for (int j = 0; j < 4; j++){
        float wv = wc[j*(CIN+1)];
        u64 wp = pk2(wv, wv);
        fma2(acc[j][0], wp, xp0);
        fma2(acc[j][1], wp, xp1);
        fma2(acc[j][2], wp, xp2);
        fma2(acc[j][3], wp, xp3);
      }
    }

    #pragma unroll
    for (int j = 0; j < 4; j++){
      const int oc = occ + toc + j;
      const float bz = bias[oc];
      float* op = out + (long long)b*out_bs + (long long)oc*HW + p0 + px;
      const float* ax  = (EPI==1) ? (aux + (long long)b*aux_bs + (long long)oc*HW + p0 + px) : nullptr;
      const float scv  = (EPI==2) ? scal[oc] : 0.f;
      const float* shp = (EPI==2) ? (shortcut + ((long long)b*COUT + oc)*HW + p0 + px) : nullptr;
      #pragma unroll
      for (int k = 0; k < 4; k++){
        float lo, hi; upk2(acc[j][k], lo, hi);
        float r0 = lo + bz, r1 = hi + bz;
        if (EPI==1){ r0 *= ax[32*k]; r1 *= ax[32*k + 16]; }
        if (EPI==2){ r0 = r0*scv + shp[32*k]; r1 = r1*scv + shp[32*k + 16]; }
        op[32*k] = r0; op[32*k + 16] = r1;
      }
    }
  }
}

// ---------------------------------------------------------------------------
// Fused branch-1 depthwise chain (per channel, 32x32 output tile):
//   in(42x42 halo) -> t1 = 1x3(lka3_w1) -> t2 = 3x1(lka3_w2) -> l3pre = 5x5dil2(lka3_w3)
//   and parallel gate: u1 = 1x3(x3a) -> x3out = 3x1(x3b)
// All intermediates in smem. One read of a1, writes l3pre + x3out.
// ---------------------------------------------------------------------------
__global__ __launch_bounds__(256)
void branch1_kernel(const float* __restrict__ in, long long in_bs,
    const float* __restrict__ l3w1, const float* __restrict__ l3b1,
    const float* __restrict__ l3w2, const float* __restrict__ l3b2,
    const float* __restrict__ l3w3, const float* __restrict__ l3b3,
    const float* __restrict__ x3aw, const float* __restrict__ x3ab,
    const float* __restrict__ x3bw, const float* __restrict__ x3bb,
    float* __restrict__ l3pre, float* __restrict__ x3out)
{
  __shared__ float sIN[42*43];
  __shared__ float sT1[42*41];
  __shared__ float sU1[34*33];
  __shared__ float sT2[40*41];
  __shared__ float wsh[42];
  // layout: [0..2]=l3w1 [3..5]=l3w2 [6..30]=l3w3 [31..33]=x3aw [34..36]=x3bw
  //         [37]=l3b1 [38]=l3b2 [39]=l3b3 [40]=x3ab [41]=x3bb

  const int c = blockIdx.z & 63, b = blockIdx.z >> 6;
  const int ty0 = blockIdx.y * 32, tx0 = blockIdx.x * 32;
  const int tid = threadIdx.x;

  if (tid < 42){
    float v;
    if      (tid < 3)  v = l3w1[c*3 + tid];
    else if (tid < 6)  v = l3w2[c*3 + tid-3];
    else if (tid < 31) v = l3w3[c*25 + tid-6];
    else if (tid < 34) v = x3aw[c*3 + tid-31];
    else if (tid < 37) v = x3bw[c*3 + tid-34];
    else if (tid == 37) v = l3b1[c];
    else if (tid == 38) v = l3b2[c];
    else if (tid == 39) v = l3b3[c];
    else if (tid == 40) v = x3ab[c];
    else                v = x3bb[c];
    wsh[tid] = v;
  }

  const float* ip = in + (long long)b*in_bs + (long long)c*HW;
  for (int i = tid; i < 42*42; i += 256){
    int sy = i / 42, sx = i - sy*42;
    int gy = ty0 + sy - 5, gx = tx0 + sx - 5;
    float v = 0.f;
    if ((unsigned)gy < 128u && (unsigned)gx < 128u) v = ip[gy*Wdim + gx];
    sIN[sy*43 + sx] = v;
  }
  __syncthreads();

  // t1 (42 rows x 40 cols): t1[r][x] covers x in [-4,36)
  {
    const float w0 = wsh[0], w1 = wsh[1], w2 = wsh[2], bz = wsh[37];
    for (int i = tid; i < 42*40; i += 256){
      int r = i / 40, x = i - r*40;
      const float* s = sIN + r*43 + x;
      sT1[r*41 + x] = w0*s[0] + w1*s[1] + w2*s[2] + bz;
    }
    // u1 (34 rows x 32 cols): rows cover y in [-1,33)
    const float a0 = wsh[31], a1 = wsh[32], a2 = wsh[33], ab = wsh[40];
    for (int i = tid; i < 34*32; i += 256){
      int r = i >> 5, x = i & 31;
      const float* s = sIN + (r+4)*43 + (x+4);
      sU1[r*33 + x] = a0*s[0] + a1*s[1] + a2*s[2] + ab;
    }
  }
  __syncthreads();

  const int oy  = tid >> 3;
  const int ox0 = (tid & 7) << 2;

  // t2 (40 x 40): rows cover y in [-4,36)
  {
    const float w0 = wsh[3], w1 = wsh[4], w2 = wsh[5], bz = wsh[38];
    for (int i = tid; i < 40*40; i += 256){
      int r = i / 40, x = i - r*40;
      sT2[r*41 + x] = w0*sT1[r*41+x] + w1*sT1[(r+1)*41+x] + w2*sT1[(r+2)*41+x] + bz;
    }
    // x3out (32x32) from u1
    const float v0 = wsh[34], v1 = wsh[35], v2 = wsh[36], vb = wsh[41];
    float4 o;
    float* d = (float*)&o;
    #pragma unroll
    for (int j = 0; j < 4; j++){
      int ox = ox0 + j;
      d[j] = v0*sU1[oy*33+ox] + v1*sU1[(oy+1)*33+ox] + v2*sU1[(oy+2)*33+ox] + vb;
    }
    *(float4*)(x3out + ((long long)b*64 + c)*HW + (long long)(ty0+oy)*Wdim + tx0 + ox0) = o;
  }
  __syncthreads();

  // l3pre (32x32): 5x5 dil2 over t2; t2 index = out + 2k
  {
    const float bz = wsh[39];
    float a0 = bz, a1 = bz, a2 = bz, a3 = bz;
    #pragma unroll
    for (int ky = 0; ky < 5; ky++){
      const float* row = sT2 + (oy + 2*ky)*41 + ox0;
      float buf[12];
      #pragma unroll
      for (int i = 0; i < 12; i++) buf[i] = row[i];
      #pragma unroll
      for (int kx = 0; kx < 5; kx++){
        const float wv = wsh[6 + ky*5 + kx];
        a0 += wv*buf[kx*2+0];
        a1 += wv*buf[kx*2+1];
        a2 += wv*buf[kx*2+2];
        a3 += wv*buf[kx*2+3];
      }
    }
    float4 r = make_float4(a0, a1, a2, a3);
    *(float4*)(l3pre + ((long long)b*64 + c)*HW + (long long)(ty0+oy)*Wdim + tx0 + ox0) = r;
  }
}

// ---------------------------------------------------------------------------
// Fused branch-2 depthwise chain (per channel, 32x32 output tile):
//   in(48x48 halo) -> v1 = 5x5(lka5_w1) -> l5pre = 7x7dil2(lka5_w2)
//   and parallel gate: x5out = 5x5(x5_w)
// ---------------------------------------------------------------------------
__global__ __launch_bounds__(256)
void branch2_kernel(const float* __restrict__ in, long long in_bs,
    const float* __restrict__ l5w1, const float* __restrict__ l5b1,
    const float* __restrict__ l5w2, const float* __restrict__ l5b2,
    const float* __restrict__ x5w,  const float* __restrict__ x5b,
    float* __restrict__ l5pre, float* __restrict__ x5out)
{
  __shared__ float sIN[48*49];
  __shared__ float sV1[44*45];
  __shared__ float wsh[104];
  // [0..24]=l5w1 [25..73]=l5w2 [74..98]=x5w [99]=l5b1 [100]=l5b2 [101]=x5b

  const int c = blockIdx.z & 63, b = blockIdx.z >> 6;
  const int ty0 = blockIdx.y * 32, tx0 = blockIdx.x * 32;
  const int tid = threadIdx.x;

  if (tid < 102){
    float v;
    if      (tid < 25) v = l5w1[c*25 + tid];
    else if (tid < 74) v = l5w2[c*49 + tid-25];
    else if (tid < 99) v = x5w[c*25 + tid-74];
    else if (tid == 99)  v = l5b1[c];
    else if (tid == 100) v = l5b2[c];
    else                 v = x5b[c];
    wsh[tid] = v;
  }

  const float* ip = in + (long long)b*in_bs + (long long)c*HW;
  for (int i = tid; i < 48*48; i += 256){
    int sy = i / 48, sx = i - sy*48;
    int gy = ty0 + sy - 8, gx = tx0 + sx - 8;
    float v = 0.f;
    if ((unsigned)gy < 128u && (unsigned)gx < 128u) v = ip[gy*Wdim + gx];
    sIN[sy*49 + sx] = v;
  }
  __syncthreads();

  const int oy  = tid >> 3;
  const int ox0 = (tid & 7) << 2;

  // v1 (44 x 44), rows/cols cover [-6,38): v1[r][cv] taps sIN[r+ky][cv+kx]
  {
    const float bz = wsh[99];
    for (int g = tid; g < 44*11; g += 256){
      int r = g / 11, c4 = (g - r*11) << 2;
      float a0 = bz, a1 = bz, a2 = bz, a3 = bz;
      #pragma unroll
      for (int ky = 0; ky < 5; ky++){
        const float* row = sIN + (r+ky)*49 + c4;
        float buf[8];
        #pragma unroll
        for (int i = 0; i < 8; i++) buf[i] = row[i];
        #pragma unroll
        for (int kx = 0; kx < 5; kx++){
          const float wv = wsh[ky*5+kx];
          a0 += wv*buf[kx+0];
          a1 += wv*buf[kx+1];
          a2 += wv*buf[kx+2];
          a3 += wv*buf[kx+3];
        }
      }
      float* d = sV1 + r*45 + c4;
      d[0]=a0; d[1]=a1; d[2]=a2; d[3]=a3;
    }
    // x5 gate (32x32): taps sIN[oy+6+ky][ox+6+kx]
    const float xb = wsh[101];
    float a0 = xb, a1 = xb, a2 = xb, a3 = xb;
    #pragma unroll
    for (int ky = 0; ky < 5; ky++){
      const float* row = sIN + (oy+6+ky)*49 + (ox0+6);
      float buf[8];
      #pragma unroll
      for (int i = 0; i < 8; i++) buf[i] = row[i];
      #pragma unroll
      for (int kx = 0; kx < 5; kx++){
        const float wv = wsh[74 + ky*5 + kx];
        a0 += wv*buf[kx+0];
        a1 += wv*buf[kx+1];
        a2 += wv*buf[kx+2];
        a3 += wv*buf[kx+3];
      }
    }
    float4 r = make_float4(a0, a1, a2, a3);
    *(float4*)(x5out + ((long long)b*64 + c)*HW + (long long)(ty0+oy)*Wdim + tx0 + ox0) = r;
  }
  __syncthreads();

  // l5pre (32x32): 7x7 dil2 over v1; v1 index = out + 2k
  {
    const float bz = wsh[100];
    float a0 = bz, a1 = bz, a2 = bz, a3 = bz;
    #pragma unroll
    for (int ky = 0; ky < 7; ky++){
      const float* row = sV1 + (oy + 2*ky)*45 + ox0;
      float buf[16];
      #pragma unroll
      for (int i = 0; i < 16; i++) buf[i] = row[i];
      #pragma unroll
      for (int kx = 0; kx < 7; kx++){
        const float wv = wsh[25 + ky*7 + kx];
        a0 += wv*buf[kx*2+0];
        a1 += wv*buf[kx*2+1];
        a2 += wv*buf[kx*2+2];
        a3 += wv*buf[kx*2+3];
      }
    }
    float4 r = make_float4(a0, a1, a2, a3);
    *(float4*)(l5pre + ((long long)b*64 + c)*HW + (long long)(ty0+oy)*Wdim + tx0 + ox0) = r;
  }
}

// ---------------------------------------------------------------------------
extern "C" void kernel_launch(void* const* d_in, const int* in_sizes, int n_in,
                              void* d_out, int out_size)
{
  const float* x    = (const float*)d_in[0];
  const float* ln_w = (const float*)d_in[1];
  const float* ln_b = (const float*)d_in[2];
  const float* scale= (const float*)d_in[3];
  const float* pf_w = (const float*)d_in[4];
  const float* pf_b = (const float*)d_in[5];
  const float* l3w1 = (const float*)d_in[6];
  const float* l3b1 = (const float*)d_in[7];
  const float* l3w2 = (const float*)d_in[8];
  const float* l3b2 = (const float*)d_in[9];
  const float* l3w3 = (const float*)d_in[10];
  const float* l3b3 = (const float*)d_in[11];
  const float* l3w4 = (const float*)d_in[12];
  const float* l3b4 = (const float*)d_in[13];
  const float* l5w1 = (const float*)d_in[14];
  const float* l5b1 = (const float*)d_in[15];
  const float* l5w2 = (const float*)d_in[16];
  const float* l5b2 = (const float*)d_in[17];
  const float* l5w3 = (const float*)d_in[18];
  const float* l5b3 = (const float*)d_in[19];
  const float* x3aw = (const float*)d_in[20];
  const float* x3ab = (const float*)d_in[21];
  const float* x3bw = (const float*)d_in[22];
  const float* x3bb = (const float*)d_in[23];
  const float* x5w  = (const float*)d_in[24];
  const float* x5b  = (const float*)d_in[25];
  const float* pl_w = (const float*)d_in[26];
  const float* pl_b = (const float*)d_in[27];
  float* out = (float*)d_out;

  float *p_h, *p_t1, *p_t2, *p_x3, *p_at;
  cudaGetSymbolAddress((void**)&p_h,  g_h);
  cudaGetSymbolAddress((void**)&p_t1, g_t1);
  cudaGetSymbolAddress((void**)&p_t2, g_t2);
  cudaGetSymbolAddress((void**)&p_x3, g_x3);
  cudaGetSymbolAddress((void**)&p_at, g_at);

  const long long BS_H = 256LL*HW, BS64 = 64LL*HW, BS128 = 128LL*HW;
  dim3 gpw(128, 16);
  dim3 gbr(4, 4, 16*64);

  // 1) LN + pf expand (128 -> 256)
  {
    auto k = pw_kernel<128,256,true,false,0>;
    size_t smb = (128*128 + 64*129) * sizeof(float);
    cudaFuncSetAttribute((const void*)k, cudaFuncAttributeMaxDynamicSharedMemorySize, (int)smb);
    k<<<gpw,256,smb>>>(x, BS128, nullptr,0, ln_w, ln_b, pf_w, pf_b,
                       nullptr,0, nullptr, nullptr, p_h, BS_H);
  }
  // 2) branch 1 fused dw chain (a1 = g_h ch 0..63) -> l3pre (t1), x3_out (x3)
  branch1_kernel<<<gbr,256>>>(p_h, BS_H, l3w1,l3b1, l3w2,l3b2, l3w3,l3b3,
                              x3aw,x3ab, x3bw,x3bb, p_t1, p_x3);
  // 3) attn_1 = pw(l3pre) * x3_out
  {
    auto k = pw_kernel<64,64,false,false,1>;
    size_t smb = (64*128 + 64*65) * sizeof(float);
    cudaFuncSetAttribute((const void*)k, cudaFuncAttributeMaxDynamicSharedMemorySize, (int)smb);
    k<<<gpw,256,smb>>>(p_t1, BS64, nullptr,0, nullptr,nullptr, l3w4, l3b4,
                       p_x3, BS64, nullptr, nullptr, p_at, BS128);
  }
  // 4) branch 2 fused dw chain (a2 = g_h ch 64..127) -> l5pre (t2), x5 (x3 reused)
  branch2_kernel<<<gbr,256>>>(p_h + 64LL*HW, BS_H, l5w1,l5b1, l5w2,l5b2,
                              x5w,x5b, p_t2, p_x3);
  // 5) attn_2 = pw(l5pre) * x5
  {
    auto k = pw_kernel<64,64,false,false,1>;
    size_t smb = (64*128 + 64*65) * sizeof(float);
    cudaFuncSetAttribute((const void*)k, cudaFuncAttributeMaxDynamicSharedMemorySize, (int)smb);
    k<<<gpw,256,smb>>>(p_t2, BS64, nullptr,0, nullptr,nullptr, l5w3, l5b3,
                       p_x3, BS64, nullptr, nullptr, p_at + 64LL*HW, BS128);
  }
  // 6) final: pl( xh * attn ) * scale + x
  {
    auto k = pw_kernel<128,128,false,true,2>;
    size_t smb = (128*128 + 64*129) * sizeof(float);
    cudaFuncSetAttribute((const void*)k, cudaFuncAttributeMaxDynamicSharedMemorySize, (int)smb);
    k<<<gpw,256,smb>>>(p_h + 128LL*HW, BS_H, p_at, BS128, nullptr, nullptr,
                       pl_w, pl_b, nullptr,0, scale, x, out, BS128);
  }
}

// round 4
// speedup vs baseline: 1.4150x; 1.2450x over previous
#include <cuda_runtime.h>
#include <cstdint>

#define HW   16384
#define Wdim 128

// ---------------- scratch ----------------
__device__ float g_h [16ULL*256*16384];  // pf out: a(0..127) | xh(128..255)
__device__ float g_t1[16ULL*128*16384];  // l3pre(0..63) | l5pre(64..127)
__device__ float g_x3[16ULL*128*16384];  // x3out(0..63) | x5(64..127)
__device__ float g_at[16ULL*128*16384];  // attn

__device__ __forceinline__ void mma_tf32(float* d, const uint32_t* a, const uint32_t* b){
  asm volatile(
    "mma.sync.aligned.m16n8k8.row.col.f32.tf32.tf32.f32 "
    "{%0,%1,%2,%3}, {%4,%5,%6,%7}, {%8,%9}, {%0,%1,%2,%3};"
    : "+f"(d[0]), "+f"(d[1]), "+f"(d[2]), "+f"(d[3])
    : "r"(a[0]), "r"(a[1]), "r"(a[2]), "r"(a[3]), "r"(b[0]), "r"(b[1]));
}

// ---------------------------------------------------------------------------
// Pointwise GEMM via mma.sync tf32: out[128oc,128px] = W[128,128] @ X[128,128px]
// per block; loops over ntiles px tiles (W staged once). Fusions:
//   LN:     per-pixel LayerNorm applied in place on the X tile (pf)
//   INMUL:  X := in*in2 on load (pl)
//   SPLITW: W = blockdiag(wA,wB) 64x64 each; warps skip the zero K half
//   EPI 0: +bias | 1: (+bias)*aux | 2: (+bias)*scale[oc]+shortcut
// ---------------------------------------------------------------------------
#define PW   132          // W smem pitch (floats)
#define PX   136          // X smem pitch (floats)
#define SM_W   0
#define SM_X   67584
#define SM_LNW 137216
#define SM_LNB 137728
#define SM_MU  138240
#define SM_RS  138752
#define SM_TOT 139264

template<bool LN, bool INMUL, bool SPLITW, int EPI>
__global__ __launch_bounds__(256, 1)
void pw_mma(const float* __restrict__ in, long long in_bs,
            const float* __restrict__ in2, long long in2_bs,
            const float* __restrict__ lnw, const float* __restrict__ lnb,
            const float* __restrict__ wA, const float* __restrict__ wB,
            const float* __restrict__ biasA, const float* __restrict__ biasB,
            const float* __restrict__ aux, long long aux_bs,
            const float* __restrict__ scal, const float* __restrict__ shortcut,
            float* __restrict__ out, long long out_bs, int ntiles)
{
  extern __shared__ char smc[];
  float* Ws   = (float*)(smc + SM_W);
  float* Xs   = (float*)(smc + SM_X);
  float* sLNw = (float*)(smc + SM_LNW);
  float* sLNb = (float*)(smc + SM_LNB);
  float* sMu  = (float*)(smc + SM_MU);
  float* sRs  = (float*)(smc + SM_RS);

  const int tid = threadIdx.x;
  const int wid = tid >> 5, lid = tid & 31;
  const int b   = blockIdx.y;
  const int mt  = blockIdx.z;

  // stage W
  if (!SPLITW){
    const float* wp = wA + (size_t)mt*128*128;
    for (int i = tid; i < 128*32; i += 256){
      int oc = i >> 5, c4 = (i & 31) << 2;
      float4 v = *(const float4*)(wp + oc*128 + c4);
      *(float4*)(Ws + oc*PW + c4) = v;
    }
  } else {
    for (int i = tid; i < 128*128; i += 256){
      int ic = i & 127, oc = i >> 7;
      float v;
      if (oc < 64) v = (ic < 64)  ? wA[oc*64 + ic]           : 0.f;
      else         v = (ic >= 64) ? wB[(oc-64)*64 + (ic-64)] : 0.f;
      Ws[oc*PW + ic] = v;
    }
  }
  if (LN && tid < 128){ sLNw[tid] = lnw[tid]; sLNb[tid] = lnb[tid]; }

  // warp tile coords
  const int ocw = (wid & 3) * 32;          // 2 x m16
  const int pxw = (wid >> 2) * 64;         // 8 x n8
  const int r   = lid >> 2;                // 0..7
  const int cq  = lid & 3;                 // 0..3

  // k-range (block-diag skip)
  const int ks0 = (SPLITW && ocw >= 64) ? 8 : 0;
  const int ks1 = SPLITW ? (ks0 + 8) : 16;

  // epilogue per-thread constants: 4 oc rows: (mi,h)
  int ocg[4]; float bzv[4], scv[4];
  #pragma unroll
  for (int mi = 0; mi < 2; mi++)
    #pragma unroll
    for (int h = 0; h < 2; h++){
      int o = ocw + mi*16 + r + h*8;
      ocg[mi*2+h] = o;
      if (!SPLITW) bzv[mi*2+h] = biasA[mt*128 + o];
      else         bzv[mi*2+h] = (o < 64) ? biasA[o] : biasB[o-64];
      scv[mi*2+h] = (EPI==2) ? scal[mt*128 + o] : 0.f;
    }

  for (int t = 0; t < ntiles; t++){
    const int px0 = (blockIdx.x * ntiles + t) * 128;
    const float* ipx  = in + (size_t)b*in_bs + px0;
    const float* ipx2 = INMUL ? (in2 + (size_t)b*in2_bs + px0) : nullptr;

    // stage X [ch][px], pitch PX
    for (int i = tid; i < 128*32; i += 256){
      int ic = i >> 5, p4 = (i & 31) << 2;
      float4 v = *(const float4*)(ipx + (size_t)ic*HW + p4);
      if (INMUL){
        float4 m = *(const float4*)(ipx2 + (size_t)ic*HW + p4);
        v.x*=m.x; v.y*=m.y; v.z*=m.z; v.w*=m.w;
      }
      *(float4*)(Xs + ic*PX + p4) = v;
    }
    __syncthreads();

    if (LN){
      if (tid < 128){
        float s = 0.f, s2 = 0.f;
        #pragma unroll 8
        for (int ic = 0; ic < 128; ic++){
          float v = Xs[ic*PX + tid]; s += v; s2 += v*v;
        }
        const float mu = s * (1.f/128.f);
        sMu[tid] = mu;
        sRs[tid] = rsqrtf(s2*(1.f/128.f) - mu*mu + 1e-6f);
      }
      __syncthreads();
      #pragma unroll 4
      for (int i = tid; i < 128*128; i += 256){
        int ic = i >> 7, px = i & 127;
        float v = Xs[ic*PX + px];
        Xs[ic*PX + px] = sLNw[ic] * ((v - sMu[px]) * sRs[px]) + sLNb[ic];
      }
      __syncthreads();
    }

    float acc[2][8][4];
    #pragma unroll
    for (int mi = 0; mi < 2; mi++)
      #pragma unroll
      for (int ni = 0; ni < 8; ni++)
        #pragma unroll
        for (int j = 0; j < 4; j++) acc[mi][ni][j] = 0.f;

    #pragma unroll 2
    for (int ks = ks0; ks < ks1; ks++){
      const int k0 = ks * 8;
      uint32_t af[2][4];
      #pragma unroll
      for (int mi = 0; mi < 2; mi++){
        const float* ab = Ws + (ocw + mi*16 + r)*PW + k0 + cq;
        af[mi][0] = __float_as_uint(ab[0]);
        af[mi][1] = __float_as_uint(ab[8*PW]);
        af[mi][2] = __float_as_uint(ab[4]);
        af[mi][3] = __float_as_uint(ab[8*PW + 4]);
      }
      uint32_t bf[8][2];
      #pragma unroll
      for (int ni = 0; ni < 8; ni++){
        const float* bb = Xs + (k0 + cq)*PX + pxw + ni*8 + r;
        bf[ni][0] = __float_as_uint(bb[0]);
        bf[ni][1] = __float_as_uint(bb[4*PX]);
      }
      #pragma unroll
      for (int mi = 0; mi < 2; mi++)
        #pragma unroll
        for (int ni = 0; ni < 8; ni++)
          mma_tf32(acc[mi][ni], af[mi], bf[ni]);
    }

    // epilogue
    #pragma unroll
    for (int mi = 0; mi < 2; mi++)
      #pragma unroll
      for (int h = 0; h < 2; h++){
        const int e  = mi*2 + h;
        const int o  = ocg[e];
        const float bz = bzv[e];
        float* op = out + (size_t)b*out_bs + (size_t)(mt*128 + o)*HW + px0 + pxw + cq*2;
        const float* axp = (EPI==1) ? (aux + (size_t)b*aux_bs + (size_t)o*HW + px0 + pxw + cq*2) : nullptr;
        const float* shp = (EPI==2) ? (shortcut + ((size_t)b*128 + o)*HW + px0 + pxw + cq*2) : nullptr;
        #pragma unroll
        for (int ni = 0; ni < 8; ni++){
          float2 v;
          v.x = acc[mi][ni][h*2+0] + bz;
          v.y = acc[mi][ni][h*2+1] + bz;
          if (EPI==1){
            float2 m = *(const float2*)(axp + ni*8);
            v.x *= m.x; v.y *= m.y;
          }
          if (EPI==2){
            float2 sh = *(const float2*)(shp + ni*8);
            v.x = v.x*scv[e] + sh.x; v.y = v.y*scv[e] + sh.y;
          }
          *(float2*)(op + ni*8) = v;
        }
      }
    __syncthreads();
  }
}

// ---------------------------------------------------------------------------
// Fused branch-1 depthwise chain (unchanged)
// ---------------------------------------------------------------------------
__global__ __launch_bounds__(256)
void branch1_kernel(const float* __restrict__ in, long long in_bs,
    const float* __restrict__ l3w1, const float* __restrict__ l3b1,
    const float* __restrict__ l3w2, const float* __restrict__ l3b2,
    const float* __restrict__ l3w3, const float* __restrict__ l3b3,
    const float* __restrict__ x3aw, const float* __restrict__ x3ab,
    const float* __restrict__ x3bw, const float* __restrict__ x3bb,
    float* __restrict__ l3pre, float* __restrict__ x3out, long long out_bs)
{
  __shared__ float sIN[42*43];
  __shared__ float sT1[42*41];
  __shared__ float sU1[34*33];
  __shared__ float sT2[40*41];
  __shared__ float wsh[42];

  const int c = blockIdx.z & 63, b = blockIdx.z >> 6;
  const int ty0 = blockIdx.y * 32, tx0 = blockIdx.x * 32;
  const int tid = threadIdx.x;

  if (tid < 42){
    float v;
    if      (tid < 3)  v = l3w1[c*3 + tid];
    else if (tid < 6)  v = l3w2[c*3 + tid-3];
    else if (tid < 31) v = l3w3[c*25 + tid-6];
    else if (tid < 34) v = x3aw[c*3 + tid-31];
    else if (tid < 37) v = x3bw[c*3 + tid-34];
    else if (tid == 37) v = l3b1[c];
    else if (tid == 38) v = l3b2[c];
    else if (tid == 39) v = l3b3[c];
    else if (tid == 40) v = x3ab[c];
    else                v = x3bb[c];
    wsh[tid] = v;
  }

  const float* ip = in + (long long)b*in_bs + (long long)c*HW;
  for (int i = tid; i < 42*42; i += 256){
    int sy = i / 42, sx = i - sy*42;
    int gy = ty0 + sy - 5, gx = tx0 + sx - 5;
    float v = 0.f;
    if ((unsigned)gy < 128u && (unsigned)gx < 128u) v = ip[gy*Wdim + gx];
    sIN[sy*43 + sx] = v;
  }
  __syncthreads();

  {
    const float w0 = wsh[0], w1 = wsh[1], w2 = wsh[2], bz = wsh[37];
    for (int i = tid; i < 42*40; i += 256){
      int r = i / 40, x = i - r*40;
      const float* s = sIN + r*43 + x;
      sT1[r*41 + x] = w0*s[0] + w1*s[1] + w2*s[2] + bz;
    }
    const float a0 = wsh[31], a1 = wsh[32], a2 = wsh[33], ab = wsh[40];
    for (int i = tid; i < 34*32; i += 256){
      int r = i >> 5, x = i & 31;
      const float* s = sIN + (r+4)*43 + (x+4);
      sU1[r*33 + x] = a0*s[0] + a1*s[1] + a2*s[2] + ab;
    }
  }
  __syncthreads();

  const int oy  = tid >> 3;
  const int ox0 = (tid & 7) << 2;

  {
    const float w0 = wsh[3], w1 = wsh[4], w2 = wsh[5], bz = wsh[38];
    for (int i = tid; i < 40*40; i += 256){
      int r = i / 40, x = i - r*40;
      sT2[r*41 + x] = w0*sT1[r*41+x] + w1*sT1[(r+1)*41+x] + w2*sT1[(r+2)*41+x] + bz;
    }
    const float v0 = wsh[34], v1 = wsh[35], v2 = wsh[36], vb = wsh[41];
    float4 o;
    float* d = (float*)&o;
    #pragma unroll
    for (int j = 0; j < 4; j++){
      int ox = ox0 + j;
      d[j] = v0*sU1[oy*33+ox] + v1*sU1[(oy+1)*33+ox] + v2*sU1[(oy+2)*33+ox] + vb;
    }
    *(float4*)(x3out + (long long)b*out_bs + (long long)c*HW
               + (long long)(ty0+oy)*Wdim + tx0 + ox0) = o;
  }
  __syncthreads();

  {
    const float bz = wsh[39];
    float a0 = bz, a1 = bz, a2 = bz, a3 = bz;
    #pragma unroll
    for (int ky = 0; ky < 5; ky++){
      const float* row = sT2 + (oy + 2*ky)*41 + ox0;
      float buf[12];
      #pragma unroll
      for (int i = 0; i < 12; i++) buf[i] = row[i];
      #pragma unroll
      for (int kx = 0; kx < 5; kx++){
        const float wv = wsh[6 + ky*5 + kx];
        a0 += wv*buf[kx*2+0];
        a1 += wv*buf[kx*2+1];
        a2 += wv*buf[kx*2+2];
        a3 += wv*buf[kx*2+3];
      }
    }
    float4 r = make_float4(a0, a1, a2, a3);
    *(float4*)(l3pre + (long long)b*out_bs + (long long)c*HW
               + (long long)(ty0+oy)*Wdim + tx0 + ox0) = r;
  }
}

// ---------------------------------------------------------------------------
// Fused branch-2 depthwise chain (unchanged)
// ---------------------------------------------------------------------------
__global__ __launch_bounds__(256)
void branch2_kernel(const float* __restrict__ in, long long in_bs,
    const float* __restrict__ l5w1, const float* __restrict__ l5b1,
    const float* __restrict__ l5w2, const float* __restrict__ l5b2,
    const float* __restrict__ x5w,  const float* __restrict__ x5b,
    float* __restrict__ l5pre, float* __restrict__ x5out, long long out_bs)
{
  __shared__ float sIN[48*49];
  __shared__ float sV1[44*45];
  __shared__ float wsh[104];

  const int c = blockIdx.z & 63, b = blockIdx.z >> 6;
  const int ty0 = blockIdx.y * 32, tx0 = blockIdx.x * 32;
  const int tid = threadIdx.x;

  if (tid < 102){
    float v;
    if      (tid < 25) v = l5w1[c*25 + tid];
    else if (tid < 74) v = l5w2[c*49 + tid-25];
    else if (tid < 99) v = x5w[c*25 + tid-74];
    else if (tid == 99)  v = l5b1[c];
    else if (tid == 100) v = l5b2[c];
    else                 v = x5b[c];
    wsh[tid] = v;
  }

  const float* ip = in + (long long)b*in_bs + (long long)c*HW;
  for (int i = tid; i < 48*48; i += 256){
    int sy = i / 48, sx = i - sy*48;
    int gy = ty0 + sy - 8, gx = tx0 + sx - 8;
    float v = 0.f;
    if ((unsigned)gy < 128u && (unsigned)gx < 128u) v = ip[gy*Wdim + gx];
    sIN[sy*49 + sx] = v;
  }
  __syncthreads();

  const int oy  = tid >> 3;
  const int ox0 = (tid & 7) << 2;

  {
    const float bz = wsh[99];
    for (int g = tid; g < 44*11; g += 256){
      int r = g / 11, c4 = (g - r*11) << 2;
      float a0 = bz, a1 = bz, a2 = bz, a3 = bz;
      #pragma unroll
      for (int ky = 0; ky < 5; ky++){
        const float* row = sIN + (r+ky)*49 + c4;
        float buf[8];
        #pragma unroll
        for (int i = 0; i < 8; i++) buf[i] = row[i];
        #pragma unroll
        for (int kx = 0; kx < 5; kx++){
          const float wv = wsh[ky*5+kx];
          a0 += wv*buf[kx+0];
          a1 += wv*buf[kx+1];
          a2 += wv*buf[kx+2];
          a3 += wv*buf[kx+3];
        }
      }
      float* d = sV1 + r*45 + c4;
      d[0]=a0; d[1]=a1; d[2]=a2; d[3]=a3;
    }
    const float xb = wsh[101];
    float a0 = xb, a1 = xb, a2 = xb, a3 = xb;
    #pragma unroll
    for (int ky = 0; ky < 5; ky++){
      const float* row = sIN + (oy+6+ky)*49 + (ox0+6);
      float buf[8];
      #pragma unroll
      for (int i = 0; i < 8; i++) buf[i] = row[i];
      #pragma unroll
      for (int kx = 0; kx < 5; kx++){
        const float wv = wsh[74 + ky*5 + kx];
        a0 += wv*buf[kx+0];
        a1 += wv*buf[kx+1];
        a2 += wv*buf[kx+2];
        a3 += wv*buf[kx+3];
      }
    }
    float4 r = make_float4(a0, a1, a2, a3);
    *(float4*)(x5out + (long long)b*out_bs + (long long)c*HW
               + (long long)(ty0+oy)*Wdim + tx0 + ox0) = r;
  }
  __syncthreads();

  {
    const float bz = wsh[100];
    float a0 = bz, a1 = bz, a2 = bz, a3 = bz;
    #pragma unroll
    for (int ky = 0; ky < 7; ky++){
      const float* row = sV1 + (oy + 2*ky)*45 + ox0;
      float buf[16];
      #pragma unroll
      for (int i = 0; i < 16; i++) buf[i] = row[i];
      #pragma unroll
      for (int kx = 0; kx < 7; kx++){
        const float wv = wsh[25 + ky*7 + kx];
        a0 += wv*buf[kx*2+0];
        a1 += wv*buf[kx*2+1];
        a2 += wv*buf[kx*2+2];
        a3 += wv*buf[kx*2+3];
      }
    }
    float4 r = make_float4(a0, a1, a2, a3);
    *(float4*)(l5pre + (long long)b*out_bs + (long long)c*HW
               + (long long)(ty0+oy)*Wdim + tx0 + ox0) = r;
  }
}

// ---------------------------------------------------------------------------
extern "C" void kernel_launch(void* const* d_in, const int* in_sizes, int n_in,
                              void* d_out, int out_size)
{
  const float* x    = (const float*)d_in[0];
  const float* ln_w = (const float*)d_in[1];
  const float* ln_b = (const float*)d_in[2];
  const float* scale= (const float*)d_in[3];
  const float* pf_w = (const float*)d_in[4];
  const float* pf_b = (const float*)d_in[5];
  const float* l3w1 = (const float*)d_in[6];
  const float* l3b1 = (const float*)d_in[7];
  const float* l3w2 = (const float*)d_in[8];
  const float* l3b2 = (const float*)d_in[9];
  const float* l3w3 = (const float*)d_in[10];
  const float* l3b3 = (const float*)d_in[11];
  const float* l3w4 = (const float*)d_in[12];
  const float* l3b4 = (const float*)d_in[13];
  const float* l5w1 = (const float*)d_in[14];
  const float* l5b1 = (const float*)d_in[15];
  const float* l5w2 = (const float*)d_in[16];
  const float* l5b2 = (const float*)d_in[17];
  const float* l5w3 = (const float*)d_in[18];
  const float* l5b3 = (const float*)d_in[19];
  const float* x3aw = (const float*)d_in[20];
  const float* x3ab = (const float*)d_in[21];
  const float* x3bw = (const float*)d_in[22];
  const float* x3bb = (const float*)d_in[23];
  const float* x5w  = (const float*)d_in[24];
  const float* x5b  = (const float*)d_in[25];
  const float* pl_w = (const float*)d_in[26];
  const float* pl_b = (const float*)d_in[27];
  float* out = (float*)d_out;

  float *p_h, *p_t1, *p_x3, *p_at;
  cudaGetSymbolAddress((void**)&p_h,  g_h);
  cudaGetSymbolAddress((void**)&p_t1, g_t1);
  cudaGetSymbolAddress((void**)&p_x3, g_x3);
  cudaGetSymbolAddress((void**)&p_at, g_at);

  const long long BS_H = 256LL*HW, BS128 = 128LL*HW;
  dim3 gbr(4, 4, 16*64);
  const int NT = 4;
  dim3 gpf(32, 16, 2), g1(32, 16, 1);

  // 1) LN + pf expand (128 -> 256)
  {
    auto k = pw_mma<true,false,false,0>;
    cudaFuncSetAttribute((const void*)k, cudaFuncAttributeMaxDynamicSharedMemorySize, SM_TOT);
    k<<<gpf,256,SM_TOT>>>(x, BS128, nullptr,0, ln_w, ln_b, pf_w, nullptr,
                          pf_b, nullptr, nullptr,0, nullptr, nullptr,
                          p_h, BS_H, NT);
  }
  // 2) fused dw branches
  branch1_kernel<<<gbr,256>>>(p_h, BS_H, l3w1,l3b1, l3w2,l3b2, l3w3,l3b3,
                              x3aw,x3ab, x3bw,x3bb, p_t1, p_x3, BS128);
  branch2_kernel<<<gbr,256>>>(p_h + 64LL*HW, BS_H, l5w1,l5b1, l5w2,l5b2,
                              x5w,x5b, p_t1 + 64LL*HW, p_x3 + 64LL*HW, BS128);
  // 3) attn = blockdiag(l3w4,l5w3) @ [l3pre;l5pre], * [x3out;x5]
  {
    auto k = pw_mma<false,false,true,1>;
    cudaFuncSetAttribute((const void*)k, cudaFuncAttributeMaxDynamicSharedMemorySize, SM_TOT);
    k<<<g1,256,SM_TOT>>>(p_t1, BS128, nullptr,0, nullptr, nullptr, l3w4, l5w3,
                         l3b4, l5b3, p_x3, BS128, nullptr, nullptr,
                         p_at, BS128, NT);
  }
  // 4) final: pl( xh * attn ) * scale + x
  {
    auto k = pw_mma<false,true,false,2>;
    cudaFuncSetAttribute((const void*)k, cudaFuncAttributeMaxDynamicSharedMemorySize, SM_TOT);
    k<<<g1,256,SM_TOT>>>(p_h + 128LL*HW, BS_H, p_at, BS128, nullptr, nullptr,
                         pl_w, nullptr, pl_b, nullptr, nullptr,0,
                         scale, x, out, BS128, NT);
  }
}

// round 5
// speedup vs baseline: 1.6543x; 1.1691x over previous
#include <cuda_runtime.h>
#include <cstdint>

#define HW   16384
#define Wdim 128

// ---------------- scratch ----------------
__device__ float g_h [16ULL*256*16384];  // pf out: a(0..127) | xh(128..255)
__device__ float g_t1[16ULL*128*16384];  // l3pre(0..63) | l5pre(64..127)
__device__ float g_x3[16ULL*128*16384];  // x3out(0..63) | x5(64..127)
__device__ float g_at[16ULL*128*16384];  // t = xh * attn

// ---------------- asm helpers ----------------
__device__ __forceinline__ uint32_t smem_u32(const void* p){
  uint32_t a;
  asm("{ .reg .u64 t; cvta.to.shared.u64 t, %1; cvt.u32.u64 %0, t; }" : "=r"(a) : "l"(p));
  return a;
}
__device__ __forceinline__ void cp16(uint32_t s, const void* g){
  asm volatile("cp.async.cg.shared.global [%0], [%1], 16;" :: "r"(s), "l"(g) : "memory");
}
__device__ __forceinline__ void cp_commit(){
  asm volatile("cp.async.commit_group;" ::: "memory");
}
__device__ __forceinline__ void cp_wait0(){
  asm volatile("cp.async.wait_group 0;" ::: "memory");
}
__device__ __forceinline__ void cp_wait1(){
  asm volatile("cp.async.wait_group 1;" ::: "memory");
}
__device__ __forceinline__ void mma_tf32(float* d, const uint32_t* a, const uint32_t* b){
  asm volatile(
    "mma.sync.aligned.m16n8k8.row.col.f32.tf32.tf32.f32 "
    "{%0,%1,%2,%3}, {%4,%5,%6,%7}, {%8,%9}, {%0,%1,%2,%3};"
    : "+f"(d[0]), "+f"(d[1]), "+f"(d[2]), "+f"(d[3])
    : "r"(a[0]), "r"(a[1]), "r"(a[2]), "r"(a[3]), "r"(b[0]), "r"(b[1]));
}

// ---------------------------------------------------------------------------
// Pointwise GEMM via mma.sync tf32, cp.async double-buffered over px tiles.
//   LN:     LayerNorm fused into B-fragment loads (pf)
//   SPLITW: W = blockdiag(wA,wB) stored compact 128x64; warps use their k half
//   EPI 0: +bias (pf) | 1: (+bias)*aux1*aux2 (attn: gate & xh) |
//       2: (+bias)*scale[oc]+shortcut (pl)
// ---------------------------------------------------------------------------
#define PX 136

template<bool LN, bool SPLITW, int EPI>
__global__ __launch_bounds__(256, 1)
void pw_mma(const float* __restrict__ in, long long in_bs,
            const float* __restrict__ lnw, const float* __restrict__ lnb,
            const float* __restrict__ wA, const float* __restrict__ wB,
            const float* __restrict__ biasA, const float* __restrict__ biasB,
            const float* __restrict__ aux1, long long aux1_bs,
            const float* __restrict__ aux2, long long aux2_bs,
            const float* __restrict__ scal, const float* __restrict__ shortcut,
            float* __restrict__ out, long long out_bs, int ntiles)
{
  constexpr int PWp   = SPLITW ? 68 : 132;
  constexpr int WBY   = 128*PWp*4;
  constexpr int XBY   = 128*PX*4;
  constexpr int LNOFF = WBY + 2*XBY;

  extern __shared__ char smc[];
  float* Ws = (float*)smc;
  float* Xb0 = (float*)(smc + WBY);
  float* Xb1 = (float*)(smc + WBY + XBY);
  float* sLNw  = (float*)(smc + LNOFF);
  float* sLNb  = (float*)(smc + LNOFF + 512);
  float* sMu   = (float*)(smc + LNOFF + 1024);
  float* sRs   = (float*)(smc + LNOFF + 1536);
  float* sPart = (float*)(smc + LNOFF + 2048);
  const uint32_t sbase = smem_u32(smc);
  const uint32_t xu0 = sbase + WBY, xu1 = sbase + WBY + XBY;

  const int tid = threadIdx.x;
  const int wid = tid >> 5, lid = tid & 31;
  const int b   = blockIdx.y;
  const int mt  = blockIdx.z;

  // stage W
  if (!SPLITW){
    const float* wp = wA + (size_t)mt*128*128;
    for (int i = tid; i < 128*32; i += 256){
      int oc = i >> 5, c4 = (i & 31) << 2;
      *(float4*)(Ws + oc*PWp + c4) = *(const float4*)(wp + oc*128 + c4);
    }
  } else {
    for (int i = tid; i < 128*16; i += 256){
      int oc = i >> 4, k4 = (i & 15) << 2;
      float4 v = (oc < 64) ? *(const float4*)(wA + oc*64 + k4)
                           : *(const float4*)(wB + (oc-64)*64 + k4);
      *(float4*)(Ws + oc*PWp + k4) = v;
    }
  }
  if (LN && tid < 128){ sLNw[tid] = lnw[tid]; sLNb[tid] = lnb[tid]; }

  // warp tile coords
  const int ocw = (wid & 3) * 32;
  const int pxw = (wid >> 2) * 64;
  const int r   = lid >> 2;
  const int cq  = lid & 3;

  constexpr int KS = SPLITW ? 8 : 16;
  const int koff = (SPLITW && ocw >= 64) ? 64 : 0;

  // epilogue constants
  int ocg[4]; float bzv[4], scv[4];
  #pragma unroll
  for (int mi = 0; mi < 2; mi++)
    #pragma unroll
    for (int h = 0; h < 2; h++){
      int o = ocw + mi*16 + r + h*8;
      ocg[mi*2+h] = o;
      if (!SPLITW) bzv[mi*2+h] = biasA[mt*128 + o];
      else         bzv[mi*2+h] = (o < 64) ? biasA[o] : biasB[o-64];
      scv[mi*2+h] = (EPI==2) ? scal[mt*128 + o] : 0.f;
    }

  // cp.async staging lambda
  auto stage = [&](int t, uint32_t xb){
    const int px0 = (blockIdx.x * ntiles + t) * 128;
    const float* ipx = in + (size_t)b*in_bs + px0;
    #pragma unroll 4
    for (int i = tid; i < 128*32; i += 256){
      int ic = i >> 5, p4 = (i & 31) << 2;
      cp16(xb + (uint32_t)(ic*PX + p4)*4u, ipx + (size_t)ic*HW + p4);
    }
    cp_commit();
  };

  stage(0, xu0);

  for (int t = 0; t < ntiles; t++){
    if (t+1 < ntiles){ stage(t+1, ((t+1)&1) ? xu1 : xu0); cp_wait1(); }
    else             { cp_wait0(); }
    __syncthreads();
    float* Xs = (t & 1) ? Xb1 : Xb0;
    const int px0 = (blockIdx.x * ntiles + t) * 128;

    if (LN){
      // stats: 256 threads, 2 halves per pixel
      const int px = tid & 127, half = tid >> 7;
      float s = 0.f, s2 = 0.f;
      #pragma unroll 8
      for (int ic = 0; ic < 64; ic++){
        float v = Xs[(half*64 + ic)*PX + px]; s += v; s2 += v*v;
      }
      sPart[tid] = s; sPart[256 + tid] = s2;
      __syncthreads();
      if (tid < 128){
        float ss = sPart[tid] + sPart[tid+128];
        float qq = sPart[256+tid] + sPart[384+tid];
        float mu = ss * (1.f/128.f);
        sMu[tid] = mu;
        sRs[tid] = rsqrtf(qq*(1.f/128.f) - mu*mu + 1e-6f);
      }
      __syncthreads();
    }

    // per-px LN constants for this thread's 8 column positions
    float muv[8], rsv[8];
    if (LN){
      #pragma unroll
      for (int ni = 0; ni < 8; ni++){
        int px = pxw + ni*8 + r;
        muv[ni] = sMu[px]; rsv[ni] = sRs[px];
      }
    }

    float acc[2][8][4];
    #pragma unroll
    for (int mi = 0; mi < 2; mi++)
      #pragma unroll
      for (int ni = 0; ni < 8; ni++)
        #pragma unroll
        for (int j = 0; j < 4; j++) acc[mi][ni][j] = 0.f;

    #pragma unroll 2
    for (int ks = 0; ks < KS; ks++){
      const int k0 = ks * 8;
      uint32_t af[2][4];
      #pragma unroll
      for (int mi = 0; mi < 2; mi++){
        const float* ab = Ws + (ocw + mi*16 + r)*PWp + k0 + cq;
        af[mi][0] = __float_as_uint(ab[0]);
        af[mi][1] = __float_as_uint(ab[8*PWp]);
        af[mi][2] = __float_as_uint(ab[4]);
        af[mi][3] = __float_as_uint(ab[8*PWp + 4]);
      }
      const int kb = koff + k0 + cq;
      float w0=0,b0=0,w4=0,b4=0;
      if (LN){ w0 = sLNw[kb]; b0 = sLNb[kb]; w4 = sLNw[kb+4]; b4 = sLNb[kb+4]; }
      uint32_t bf[8][2];
      #pragma unroll
      for (int ni = 0; ni < 8; ni++){
        const float* bb = Xs + kb*PX + pxw + ni*8 + r;
        float x0 = bb[0], x4 = bb[4*PX];
        if (LN){
          x0 = (x0 - muv[ni]) * (w0 * rsv[ni]) + b0;
          x4 = (x4 - muv[ni]) * (w4 * rsv[ni]) + b4;
        }
        bf[ni][0] = __float_as_uint(x0);
        bf[ni][1] = __float_as_uint(x4);
      }
      #pragma unroll
      for (int mi = 0; mi < 2; mi++)
        #pragma unroll
        for (int ni = 0; ni < 8; ni++)
          mma_tf32(acc[mi][ni], af[mi], bf[ni]);
    }

    // epilogue
    #pragma unroll
    for (int mi = 0; mi < 2; mi++)
      #pragma unroll
      for (int h = 0; h < 2; h++){
        const int e = mi*2 + h;
        const int o = ocg[e];
        const float bz = bzv[e];
        const int pc = px0 + pxw + cq*2;
        float* op = out + (size_t)b*out_bs + (size_t)(mt*128 + o)*HW + pc;
        const float* a1p = (EPI==1) ? (aux1 + (size_t)b*aux1_bs + (size_t)o*HW + pc) : nullptr;
        const float* a2p = (EPI==1) ? (aux2 + (size_t)b*aux2_bs + (size_t)o*HW + pc) : nullptr;
        const float* shp = (EPI==2) ? (shortcut + ((size_t)b*128 + o)*HW + pc) : nullptr;
        #pragma unroll
        for (int ni = 0; ni < 8; ni++){
          float2 v;
          v.x = acc[mi][ni][h*2+0] + bz;
          v.y = acc[mi][ni][h*2+1] + bz;
          if (EPI==1){
            float2 m1 = *(const float2*)(a1p + ni*8);
            float2 m2 = *(const float2*)(a2p + ni*8);
            v.x *= m1.x * m2.x; v.y *= m1.y * m2.y;
          }
          if (EPI==2){
            float2 sh = *(const float2*)(shp + ni*8);
            v.x = v.x*scv[e] + sh.x; v.y = v.y*scv[e] + sh.y;
          }
          *(float2*)(op + ni*8) = v;
        }
      }
    __syncthreads();
  }
}

// ---------------------------------------------------------------------------
// Fused branch-1 depthwise chain: 32x64 output tile, 8 px/thread.
// ---------------------------------------------------------------------------
__global__ __launch_bounds__(256)
void branch1_kernel(const float* __restrict__ in, long long in_bs,
    const float* __restrict__ l3w1, const float* __restrict__ l3b1,
    const float* __restrict__ l3w2, const float* __restrict__ l3b2,
    const float* __restrict__ l3w3, const float* __restrict__ l3b3,
    const float* __restrict__ x3aw, const float* __restrict__ x3ab,
    const float* __restrict__ x3bw, const float* __restrict__ x3bb,
    float* __restrict__ l3pre, float* __restrict__ x3out, long long out_bs)
{
  __shared__ float sIN[42*75];
  __shared__ float sT1[42*73];
  __shared__ float sU1[34*65];
  __shared__ float sT2[40*73];
  __shared__ float wsh[42];

  const int c = blockIdx.z & 63, b = blockIdx.z >> 6;
  const int ty0 = blockIdx.y * 32, tx0 = blockIdx.x * 64;
  const int tid = threadIdx.x;

  if (tid < 42){
    float v;
    if      (tid < 3)  v = l3w1[c*3 + tid];
    else if (tid < 6)  v = l3w2[c*3 + tid-3];
    else if (tid < 31) v = l3w3[c*25 + tid-6];
    else if (tid < 34) v = x3aw[c*3 + tid-31];
    else if (tid < 37) v = x3bw[c*3 + tid-34];
    else if (tid == 37) v = l3b1[c];
    else if (tid == 38) v = l3b2[c];
    else if (tid == 39) v = l3b3[c];
    else if (tid == 40) v = x3ab[c];
    else                v = x3bb[c];
    wsh[tid] = v;
  }

  const float* ip = in + (long long)b*in_bs + (long long)c*HW;
  for (int i = tid; i < 42*74; i += 256){
    int sy = i / 74, sx = i - sy*74;
    int gy = ty0 + sy - 5, gx = tx0 + sx - 5;
    float v = 0.f;
    if ((unsigned)gy < 128u && (unsigned)gx < 128u) v = ip[gy*Wdim + gx];
    sIN[sy*75 + sx] = v;
  }
  __syncthreads();

  {
    const float w0 = wsh[0], w1 = wsh[1], w2 = wsh[2], bz = wsh[37];
    for (int i = tid; i < 42*72; i += 256){
      int r = i / 72, x = i - r*72;
      const float* s = sIN + r*75 + x;
      sT1[r*73 + x] = w0*s[0] + w1*s[1] + w2*s[2] + bz;
    }
    const float a0 = wsh[31], a1 = wsh[32], a2 = wsh[33], ab = wsh[40];
    for (int i = tid; i < 34*64; i += 256){
      int r = i >> 6, x = i & 63;
      const float* s = sIN + (r+4)*75 + x + 4;
      sU1[r*65 + x] = a0*s[0] + a1*s[1] + a2*s[2] + ab;
    }
  }
  __syncthreads();

  const int oy  = tid >> 3;
  const int ox0 = (tid & 7) << 3;

  {
    const float w0 = wsh[3], w1 = wsh[4], w2 = wsh[5], bz = wsh[38];
    for (int i = tid; i < 40*72; i += 256){
      int r = i / 72, x = i - r*72;
      sT2[r*73 + x] = w0*sT1[r*73+x] + w1*sT1[(r+1)*73+x] + w2*sT1[(r+2)*73+x] + bz;
    }
    const float v0 = wsh[34], v1 = wsh[35], v2 = wsh[36], vb = wsh[41];
    float o8[8];
    #pragma unroll
    for (int j = 0; j < 8; j++){
      int ox = ox0 + j;
      o8[j] = v0*sU1[oy*65+ox] + v1*sU1[(oy+1)*65+ox] + v2*sU1[(oy+2)*65+ox] + vb;
    }
    float* dp = x3out + (long long)b*out_bs + (long long)c*HW
              + (long long)(ty0+oy)*Wdim + tx0 + ox0;
    *(float4*)dp       = make_float4(o8[0], o8[1], o8[2], o8[3]);
    *(float4*)(dp + 4) = make_float4(o8[4], o8[5], o8[6], o8[7]);
  }
  __syncthreads();

  {
    const float bz = wsh[39];
    float a[8];
    #pragma unroll
    for (int j = 0; j < 8; j++) a[j] = bz;
    #pragma unroll
    for (int ky = 0; ky < 5; ky++){
      const float* row = sT2 + (oy + 2*ky)*73 + ox0;
      float buf[16];
      #pragma unroll
      for (int i = 0; i < 16; i++) buf[i] = row[i];
      #pragma unroll
      for (int kx = 0; kx < 5; kx++){
        const float wv = wsh[6 + ky*5 + kx];
        #pragma unroll
        for (int j = 0; j < 8; j++) a[j] += wv * buf[kx*2 + j];
      }
    }
    float* dp = l3pre + (long long)b*out_bs + (long long)c*HW
              + (long long)(ty0+oy)*Wdim + tx0 + ox0;
    *(float4*)dp       = make_float4(a[0], a[1], a[2], a[3]);
    *(float4*)(dp + 4) = make_float4(a[4], a[5], a[6], a[7]);
  }
}

// ---------------------------------------------------------------------------
// Fused branch-2 depthwise chain: 32x64 output tile, 8 px/thread.
// ---------------------------------------------------------------------------
__global__ __launch_bounds__(256)
void branch2_kernel(const float* __restrict__ in, long long in_bs,
    const float* __restrict__ l5w1, const float* __restrict__ l5b1,
    const float* __restrict__ l5w2, const float* __restrict__ l5b2,
    const float* __restrict__ x5w,  const float* __restrict__ x5b,
    float* __restrict__ l5pre, float* __restrict__ x5out, long long out_bs)
{
  __shared__ float sIN[48*81];
  __shared__ float sV1[44*77];
  __shared__ float wsh[104];

  const int c = blockIdx.z & 63, b = blockIdx.z >> 6;
  const int ty0 = blockIdx.y * 32, tx0 = blockIdx.x * 64;
  const int tid = threadIdx.x;

  if (tid < 102){
    float v;
    if      (tid < 25) v = l5w1[c*25 + tid];
    else if (tid < 74) v = l5w2[c*49 + tid-25];
    else if (tid < 99) v = x5w[c*25 + tid-74];
    else if (tid == 99)  v = l5b1[c];
    else if (tid == 100) v = l5b2[c];
    else                 v = x5b[c];
    wsh[tid] = v;
  }

  const float* ip = in + (long long)b*in_bs + (long long)c*HW;
  for (int i = tid; i < 48*80; i += 256){
    int sy = i / 80, sx = i - sy*80;
    int gy = ty0 + sy - 8, gx = tx0 + sx - 8;
    float v = 0.f;
    if ((unsigned)gy < 128u && (unsigned)gx < 128u) v = ip[gy*Wdim + gx];
    sIN[sy*81 + sx] = v;
  }
  __syncthreads();

  const int oy  = tid >> 3;
  const int ox0 = (tid & 7) << 3;

  {
    // v1 (44 x 76), strips of 4
    const float bz = wsh[99];
    for (int g = tid; g < 44*19; g += 256){
      int r = g / 19, c4 = (g - r*19) << 2;
      float a0 = bz, a1 = bz, a2 = bz, a3 = bz;
      #pragma unroll
      for (int ky = 0; ky < 5; ky++){
        const float* row = sIN + (r+ky)*81 + c4;
        float buf[8];
        #pragma unroll
        for (int i = 0; i < 8; i++) buf[i] = row[i];
        #pragma unroll
        for (int kx = 0; kx < 5; kx++){
          const float wv = wsh[ky*5+kx];
          a0 += wv*buf[kx+0];
          a1 += wv*buf[kx+1];
          a2 += wv*buf[kx+2];
          a3 += wv*buf[kx+3];
        }
      }
      float* d = sV1 + r*77 + c4;
      d[0]=a0; d[1]=a1; d[2]=a2; d[3]=a3;
    }
    // gate x5out (8 px/thread)
    const float xb = wsh[101];
    float a[8];
    #pragma unroll
    for (int j = 0; j < 8; j++) a[j] = xb;
    #pragma unroll
    for (int ky = 0; ky < 5; ky++){
      const float* row = sIN + (oy+6+ky)*81 + ox0 + 6;
      float buf[12];
      #pragma unroll
      for (int i = 0; i < 12; i++) buf[i] = row[i];
      #pragma unroll
      for (int kx = 0; kx < 5; kx++){
        const float wv = wsh[74 + ky*5 + kx];
        #pragma unroll
        for (int j = 0; j < 8; j++) a[j] += wv * buf[kx + j];
      }
    }
    float* dp = x5out + (long long)b*out_bs + (long long)c*HW
              + (long long)(ty0+oy)*Wdim + tx0 + ox0;
    *(float4*)dp       = make_float4(a[0], a[1], a[2], a[3]);
    *(float4*)(dp + 4) = make_float4(a[4], a[5], a[6], a[7]);
  }
  __syncthreads();

  {
    const float bz = wsh[100];
    float a[8];
    #pragma unroll
    for (int j = 0; j < 8; j++) a[j] = bz;
    #pragma unroll
    for (int ky = 0; ky < 7; ky++){
      const float* row = sV1 + (oy + 2*ky)*77 + ox0;
      float buf[20];
      #pragma unroll
      for (int i = 0; i < 20; i++) buf[i] = row[i];
      #pragma unroll
      for (int kx = 0; kx < 7; kx++){
        const float wv = wsh[25 + ky*7 + kx];
        #pragma unroll
        for (int j = 0; j < 8; j++) a[j] += wv * buf[kx*2 + j];
      }
    }
    float* dp = l5pre + (long long)b*out_bs + (long long)c*HW
              + (long long)(ty0+oy)*Wdim + tx0 + ox0;
    *(float4*)dp       = make_float4(a[0], a[1], a[2], a[3]);
    *(float4*)(dp + 4) = make_float4(a[4], a[5], a[6], a[7]);
  }
}

// ---------------------------------------------------------------------------
extern "C" void kernel_launch(void* const* d_in, const int* in_sizes, int n_in,
                              void* d_out, int out_size)
{
  const float* x    = (const float*)d_in[0];
  const float* ln_w = (const float*)d_in[1];
  const float* ln_b = (const float*)d_in[2];
  const float* scale= (const float*)d_in[3];
  const float* pf_w = (const float*)d_in[4];
  const float* pf_b = (const float*)d_in[5];
  const float* l3w1 = (const float*)d_in[6];
  const float* l3b1 = (const float*)d_in[7];
  const float* l3w2 = (const float*)d_in[8];
  const float* l3b2 = (const float*)d_in[9];
  const float* l3w3 = (const float*)d_in[10];
  const float* l3b3 = (const float*)d_in[11];
  const float* l3w4 = (const float*)d_in[12];
  const float* l3b4 = (const float*)d_in[13];
  const float* l5w1 = (const float*)d_in[14];
  const float* l5b1 = (const float*)d_in[15];
  const float* l5w2 = (const float*)d_in[16];
  const float* l5b2 = (const float*)d_in[17];
  const float* l5w3 = (const float*)d_in[18];
  const float* l5b3 = (const float*)d_in[19];
  const float* x3aw = (const float*)d_in[20];
  const float* x3ab = (const float*)d_in[21];
  const float* x3bw = (const float*)d_in[22];
  const float* x3bb = (const float*)d_in[23];
  const float* x5w  = (const float*)d_in[24];
  const float* x5b  = (const float*)d_in[25];
  const float* pl_w = (const float*)d_in[26];
  const float* pl_b = (const float*)d_in[27];
  float* out = (float*)d_out;

  float *p_h, *p_t1, *p_x3, *p_at;
  cudaGetSymbolAddress((void**)&p_h,  g_h);
  cudaGetSymbolAddress((void**)&p_t1, g_t1);
  cudaGetSymbolAddress((void**)&p_x3, g_x3);
  cudaGetSymbolAddress((void**)&p_at, g_at);

  const long long BS_H = 256LL*HW, BS128 = 128LL*HW;
  dim3 gbr(2, 4, 16*64);
  const int NT = 4;
  dim3 gpf(32, 16, 2), g1(32, 16, 1);

  const int SM_PF   = 128*132*4 + 2*128*PX*4 + 4096;   // 210944
  const int SM_ATTN = 128*68*4  + 2*128*PX*4;          // 174080
  const int SM_PL   = 128*132*4 + 2*128*PX*4;          // 206848

  // 1) LN + pf expand (128 -> 256)
  {
    auto k = pw_mma<true,false,0>;
    cudaFuncSetAttribute((const void*)k, cudaFuncAttributeMaxDynamicSharedMemorySize, SM_PF);
    k<<<gpf,256,SM_PF>>>(x, BS128, ln_w, ln_b, pf_w, nullptr, pf_b, nullptr,
                         nullptr,0, nullptr,0, nullptr, nullptr,
                         p_h, BS_H, NT);
  }
  // 2) fused dw branches
  branch1_kernel<<<gbr,256>>>(p_h, BS_H, l3w1,l3b1, l3w2,l3b2, l3w3,l3b3,
                              x3aw,x3ab, x3bw,x3bb, p_t1, p_x3, BS128);
  branch2_kernel<<<gbr,256>>>(p_h + 64LL*HW, BS_H, l5w1,l5b1, l5w2,l5b2,
                              x5w,x5b, p_t1 + 64LL*HW, p_x3 + 64LL*HW, BS128);
  // 3) t = ( blockdiag(l3w4,l5w3) @ [l3pre;l5pre] + bias ) * gate * xh
  {
    auto k = pw_mma<false,true,1>;
    cudaFuncSetAttribute((const void*)k, cudaFuncAttributeMaxDynamicSharedMemorySize, SM_ATTN);
    k<<<g1,256,SM_ATTN>>>(p_t1, BS128, nullptr, nullptr, l3w4, l5w3,
                          l3b4, l5b3, p_x3, BS128, p_h + 128LL*HW, BS_H,
                          nullptr, nullptr, p_at, BS128, NT);
  }
  // 4) final: pl(t) * scale + x
  {
    auto k = pw_mma<false,false,2>;
    cudaFuncSetAttribute((const void*)k, cudaFuncAttributeMaxDynamicSharedMemorySize, SM_PL);
    k<<<g1,256,SM_PL>>>(p_at, BS128, nullptr, nullptr, pl_w, nullptr,
                        pl_b, nullptr, nullptr,0, nullptr,0,
                        scale, x, out, BS128, NT);
  }
}

// round 6
// speedup vs baseline: 1.8275x; 1.1047x over previous
#include <cuda_runtime.h>
#include <cuda_bf16.h>
#include <cstdint>

#define HW   16384
#define Wdim 128

// ---------------- scratch (bf16 intermediates) ----------------
__device__ __nv_bfloat16 g_h [16ULL*256*16384];  // pf out: a(0..127) | xh(128..255)
__device__ __nv_bfloat16 g_t1[16ULL*128*16384];  // l3pre(0..63) | l5pre(64..127)
__device__ __nv_bfloat16 g_x3[16ULL*128*16384];  // x3out(0..63) | x5(64..127)
__device__ __nv_bfloat16 g_at[16ULL*128*16384];  // t = xh * attn

// ---------------- helpers ----------------
__device__ __forceinline__ uint32_t smem_u32(const void* p){
  uint32_t a;
  asm("{ .reg .u64 t; cvta.to.shared.u64 t, %1; cvt.u32.u64 %0, t; }" : "=r"(a) : "l"(p));
  return a;
}
__device__ __forceinline__ void cp16(uint32_t s, const void* g){
  asm volatile("cp.async.cg.shared.global [%0], [%1], 16;" :: "r"(s), "l"(g) : "memory");
}
__device__ __forceinline__ void cp_commit(){ asm volatile("cp.async.commit_group;" ::: "memory"); }
__device__ __forceinline__ void cp_wait0(){ asm volatile("cp.async.wait_group 0;" ::: "memory"); }
__device__ __forceinline__ void cp_wait1(){ asm volatile("cp.async.wait_group 1;" ::: "memory"); }
__device__ __forceinline__ void mma_tf32(float* d, const uint32_t* a, const uint32_t* b){
  asm volatile(
    "mma.sync.aligned.m16n8k8.row.col.f32.tf32.tf32.f32 "
    "{%0,%1,%2,%3}, {%4,%5,%6,%7}, {%8,%9}, {%0,%1,%2,%3};"
    : "+f"(d[0]), "+f"(d[1]), "+f"(d[2]), "+f"(d[3])
    : "r"(a[0]), "r"(a[1]), "r"(a[2]), "r"(a[3]), "r"(b[0]), "r"(b[1]));
}
__device__ __forceinline__ uint32_t pkbf(float a, float b){
  __nv_bfloat162 t = __floats2bfloat162_rn(a, b);
  return *reinterpret_cast<uint32_t*>(&t);
}
template<typename T> __device__ __forceinline__ float tfv(T v);
template<> __device__ __forceinline__ float tfv<float>(float v){ return v; }
template<> __device__ __forceinline__ float tfv<__nv_bfloat16>(__nv_bfloat16 v){ return __bfloat162float(v); }

// ---------------------------------------------------------------------------
// Pointwise GEMM, tf32 mma.sync, cp.async double-buffered.
//   TIN/TOUT/TW: float or __nv_bfloat16 storage types
//   LN: LayerNorm fused into B-fragment loads (pf; TIN=float only)
//   SPLITW: W = blockdiag compact 128x64
//   AUXPIPE: stage aux1/aux2 via cp.async (EPI==1)
//   EPI 0: +bias | 1: (+bias)*aux1*aux2 | 2: (+bias)*scale[oc]+shortcut(f32)
// ---------------------------------------------------------------------------
#define PX 136

template<bool LN, bool SPLITW, int EPI, typename TIN, typename TOUT, typename TW, bool AUXPIPE>
__global__ __launch_bounds__(256, 1)
void pw_mma(const TIN* __restrict__ in, long long in_bs,
            const float* __restrict__ lnw, const float* __restrict__ lnb,
            const float* __restrict__ wA, const float* __restrict__ wB,
            const float* __restrict__ biasA, const float* __restrict__ biasB,
            const __nv_bfloat16* __restrict__ aux1, long long aux1_bs,
            const __nv_bfloat16* __restrict__ aux2, long long aux2_bs,
            const float* __restrict__ scal, const float* __restrict__ shortcut,
            TOUT* __restrict__ out, long long out_bs, int ntiles)
{
  constexpr int PWp = SPLITW ? 68 : 132;
  constexpr int WBY = 128*PWp*(int)sizeof(TW);
  constexpr int XBY = 128*PX*(int)sizeof(TIN);
  constexpr int ABY = 128*PX*2;
  constexpr int AOFF  = WBY + 2*XBY;
  constexpr int LNOFF = AOFF + (AUXPIPE ? 4*ABY : 0);

  extern __shared__ char smc[];
  TW*  Ws  = (TW*)smc;
  TIN* Xb0 = (TIN*)(smc + WBY);
  TIN* Xb1 = (TIN*)(smc + WBY + XBY);
  float* sLNw  = (float*)(smc + LNOFF);
  float* sLNb  = (float*)(smc + LNOFF + 512);
  float* sMu   = (float*)(smc + LNOFF + 1024);
  float* sRs   = (float*)(smc + LNOFF + 1536);
  float* sPart = (float*)(smc + LNOFF + 2048);
  const uint32_t sbase = smem_u32(smc);
  const uint32_t xu0 = sbase + WBY, xu1 = sbase + WBY + XBY;

  const int tid = threadIdx.x;
  const int wid = tid >> 5, lid = tid & 31;
  const int b   = blockIdx.y;
  const int mt  = blockIdx.z;

  // ---- stage W (convert to TW) ----
  if (!SPLITW){
    const float* wp = wA + (size_t)mt*128*128;
    for (int i = tid; i < 128*32; i += 256){
      int oc = i >> 5, c4 = (i & 31) << 2;
      float4 v = *(const float4*)(wp + oc*128 + c4);
      if constexpr (sizeof(TW) == 2){
        uint32_t* d = (uint32_t*)(Ws + oc*PWp + c4);
        d[0] = pkbf(v.x, v.y); d[1] = pkbf(v.z, v.w);
      } else {
        *(float4*)((float*)Ws + oc*PWp + c4) = v;
      }
    }
  } else {
    for (int i = tid; i < 128*16; i += 256){
      int oc = i >> 4, k4 = (i & 15) << 2;
      float4 v = (oc < 64) ? *(const float4*)(wA + oc*64 + k4)
                           : *(const float4*)(wB + (oc-64)*64 + k4);
      if constexpr (sizeof(TW) == 2){
        uint32_t* d = (uint32_t*)(Ws + oc*PWp + k4);
        d[0] = pkbf(v.x, v.y); d[1] = pkbf(v.z, v.w);
      } else {
        *(float4*)((float*)Ws + oc*PWp + k4) = v;
      }
    }
  }
  if (LN && tid < 128){ sLNw[tid] = lnw[tid]; sLNb[tid] = lnb[tid]; }

  const int ocw = (wid & 3) * 32;
  const int pxw = (wid >> 2) * 64;
  const int r   = lid >> 2;
  const int cq  = lid & 3;

  constexpr int KS = SPLITW ? 8 : 16;
  const int koff = (SPLITW && ocw >= 64) ? 64 : 0;

  int ocg[4]; float bzv[4], scv[4];
  #pragma unroll
  for (int mi = 0; mi < 2; mi++)
    #pragma unroll
    for (int h = 0; h < 2; h++){
      int o = ocw + mi*16 + r + h*8;
      ocg[mi*2+h] = o;
      if (!SPLITW) bzv[mi*2+h] = biasA[mt*128 + o];
      else         bzv[mi*2+h] = (o < 64) ? biasA[o] : biasB[o-64];
      scv[mi*2+h] = (EPI==2) ? scal[mt*128 + o] : 0.f;
    }

  auto stage = [&](int t){
    const int px0 = (blockIdx.x * ntiles + t) * 128;
    const uint32_t xb = (t & 1) ? xu1 : xu0;
    const TIN* ipx = in + (size_t)b*in_bs + px0;
    constexpr int CHK = 16/(int)sizeof(TIN);
    constexpr int NCH = 128/CHK;
    #pragma unroll 4
    for (int i = tid; i < 128*NCH; i += 256){
      int ic = i / NCH, pc = (i % NCH) * CHK;
      cp16(xb + (uint32_t)(ic*PX + pc)*(uint32_t)sizeof(TIN), ipx + (size_t)ic*HW + pc);
    }
    if constexpr (AUXPIPE){
      const uint32_t a1b = sbase + AOFF + (uint32_t)(t & 1)*ABY;
      const uint32_t a2b = sbase + AOFF + 2*ABY + (uint32_t)(t & 1)*ABY;
      const __nv_bfloat16* a1 = aux1 + (size_t)b*aux1_bs + px0;
      const __nv_bfloat16* a2 = aux2 + (size_t)b*aux2_bs + px0;
      #pragma unroll 4
      for (int i = tid; i < 128*16; i += 256){
        int ic = i >> 4, pc = (i & 15) << 3;
        cp16(a1b + (uint32_t)(ic*PX + pc)*2u, a1 + (size_t)ic*HW + pc);
        cp16(a2b + (uint32_t)(ic*PX + pc)*2u, a2 + (size_t)ic*HW + pc);
      }
    }
    cp_commit();
  };

  stage(0);

  for (int t = 0; t < ntiles; t++){
    if (t+1 < ntiles){ stage(t+1); cp_wait1(); }
    else             { cp_wait0(); }
    __syncthreads();
    TIN* Xs = (t & 1) ? Xb1 : Xb0;
    const int px0 = (blockIdx.x * ntiles + t) * 128;

    if constexpr (LN){
      const int px = tid & 127, half = tid >> 7;
      float s = 0.f, s2 = 0.f;
      #pragma unroll 8
      for (int ic = 0; ic < 64; ic++){
        float v = tfv(Xs[(half*64 + ic)*PX + px]); s += v; s2 += v*v;
      }
      sPart[tid] = s; sPart[256 + tid] = s2;
      __syncthreads();
      if (tid < 128){
        float ss = sPart[tid] + sPart[tid+128];
        float qq = sPart[256+tid] + sPart[384+tid];
        float mu = ss * (1.f/128.f);
        sMu[tid] = mu;
        sRs[tid] = rsqrtf(qq*(1.f/128.f) - mu*mu + 1e-6f);
      }
      __syncthreads();
    }

    float muv[8], rsv[8];
    if constexpr (LN){
      #pragma unroll
      for (int ni = 0; ni < 8; ni++){
        int px = pxw + ni*8 + r;
        muv[ni] = sMu[px]; rsv[ni] = sRs[px];
      }
    }

    float acc[2][8][4];
    #pragma unroll
    for (int mi = 0; mi < 2; mi++)
      #pragma unroll
      for (int ni = 0; ni < 8; ni++)
        #pragma unroll
        for (int j = 0; j < 4; j++) acc[mi][ni][j] = 0.f;

    #pragma unroll 2
    for (int ks = 0; ks < KS; ks++){
      const int k0 = ks * 8;
      uint32_t af[2][4];
      #pragma unroll
      for (int mi = 0; mi < 2; mi++){
        const TW* ab = Ws + (ocw + mi*16 + r)*PWp + k0 + cq;
        af[mi][0] = __float_as_uint(tfv(ab[0]));
        af[mi][1] = __float_as_uint(tfv(ab[8*PWp]));
        af[mi][2] = __float_as_uint(tfv(ab[4]));
        af[mi][3] = __float_as_uint(tfv(ab[8*PWp + 4]));
      }
      const int kb = koff + k0 + cq;
      float w0=0,bb0=0,w4=0,bb4=0;
      if constexpr (LN){ w0 = sLNw[kb]; bb0 = sLNb[kb]; w4 = sLNw[kb+4]; bb4 = sLNb[kb+4]; }
      uint32_t bf[8][2];
      #pragma unroll
      for (int ni = 0; ni < 8; ni++){
        const TIN* bb = Xs + kb*PX + pxw + ni*8 + r;
        float x0 = tfv(bb[0]), x4 = tfv(bb[4*PX]);
        if constexpr (LN){
          x0 = (x0 - muv[ni]) * (w0 * rsv[ni]) + bb0;
          x4 = (x4 - muv[ni]) * (w4 * rsv[ni]) + bb4;
        }
        bf[ni][0] = __float_as_uint(x0);
        bf[ni][1] = __float_as_uint(x4);
      }
      #pragma unroll
      for (int mi = 0; mi < 2; mi++)
        #pragma unroll
        for (int ni = 0; ni < 8; ni++)
          mma_tf32(acc[mi][ni], af[mi], bf[ni]);
    }

    // epilogue
    const __nv_bfloat16* A1s = (const __nv_bfloat16*)(smc + AOFF + (t & 1)*ABY);
    const __nv_bfloat16* A2s = (const __nv_bfloat16*)(smc + AOFF + 2*ABY + (t & 1)*ABY);
    #pragma unroll
    for (int mi = 0; mi < 2; mi++)
      #pragma unroll
      for (int h = 0; h < 2; h++){
        const int e = mi*2 + h;
        const int o = ocg[e];
        const float bz = bzv[e];
        const int pcl = pxw + cq*2;
        const int pc  = px0 + pcl;
        TOUT* op = out + (size_t)b*out_bs + (size_t)(mt*128 + o)*HW + pc;
        const float* shp = (EPI==2) ? (shortcut + ((size_t)b*128 + o)*HW + pc) : nullptr;
        #pragma unroll
        for (int ni = 0; ni < 8; ni++){
          float vx = acc[mi][ni][h*2+0] + bz;
          float vy = acc[mi][ni][h*2+1] + bz;
          if constexpr (EPI==1){
            __nv_bfloat162 m1 = *(const __nv_bfloat162*)(A1s + o*PX + pcl + ni*8);
            __nv_bfloat162 m2 = *(const __nv_bfloat162*)(A2s + o*PX + pcl + ni*8);
            float2 f1 = __bfloat1622float2(m1);
            float2 f2 = __bfloat1622float2(m2);
            vx *= f1.x * f2.x; vy *= f1.y * f2.y;
          }
          if constexpr (EPI==2){
            float2 sh = *(const float2*)(shp + ni*8);
            vx = vx*scv[e] + sh.x; vy = vy*scv[e] + sh.y;
          }
          if constexpr (sizeof(TOUT) == 2){
            *(uint32_t*)(op + ni*8) = pkbf(vx, vy);
          } else {
            *(float2*)((float*)op + ni*8) = make_float2(vx, vy);
          }
        }
      }
    __syncthreads();
  }
}

// ---------------------------------------------------------------------------
// Fused branch-1 depthwise chain: 32x64 output tile, bf16 I/O.
// ---------------------------------------------------------------------------
__global__ __launch_bounds__(256)
void branch1_kernel(const __nv_bfloat16* __restrict__ in, long long in_bs,
    const float* __restrict__ l3w1, const float* __restrict__ l3b1,
    const float* __restrict__ l3w2, const float* __restrict__ l3b2,
    const float* __restrict__ l3w3, const float* __restrict__ l3b3,
    const float* __restrict__ x3aw, const float* __restrict__ x3ab,
    const float* __restrict__ x3bw, const float* __restrict__ x3bb,
    __nv_bfloat16* __restrict__ l3pre, __nv_bfloat16* __restrict__ x3out,
    long long out_bs)
{
  __shared__ float sIN[42*75];
  __shared__ float sT1[42*73];
  __shared__ float sU1[34*65];
  __shared__ float sT2[40*73];
  __shared__ float wsh[42];

  const int c = blockIdx.z & 63, b = blockIdx.z >> 6;
  const int ty0 = blockIdx.y * 32, tx0 = blockIdx.x * 64;
  const int tid = threadIdx.x;

  if (tid < 42){
    float v;
    if      (tid < 3)  v = l3w1[c*3 + tid];
    else if (tid < 6)  v = l3w2[c*3 + tid-3];
    else if (tid < 31) v = l3w3[c*25 + tid-6];
    else if (tid < 34) v = x3aw[c*3 + tid-31];
    else if (tid < 37) v = x3bw[c*3 + tid-34];
    else if (tid == 37) v = l3b1[c];
    else if (tid == 38) v = l3b2[c];
    else if (tid == 39) v = l3b3[c];
    else if (tid == 40) v = x3ab[c];
    else                v = x3bb[c];
    wsh[tid] = v;
  }

  const __nv_bfloat16* ip = in + (long long)b*in_bs + (long long)c*HW;
  for (int i = tid; i < 42*74; i += 256){
    int sy = i / 74, sx = i - sy*74;
    int gy = ty0 + sy - 5, gx = tx0 + sx - 5;
    float v = 0.f;
    if ((unsigned)gy < 128u && (unsigned)gx < 128u) v = __bfloat162float(ip[gy*Wdim + gx]);
    sIN[sy*75 + sx] = v;
  }
  __syncthreads();

  {
    const float w0 = wsh[0], w1 = wsh[1], w2 = wsh[2], bz = wsh[37];
    for (int i = tid; i < 42*72; i += 256){
      int r = i / 72, x = i - r*72;
      const float* s = sIN + r*75 + x;
      sT1[r*73 + x] = w0*s[0] + w1*s[1] + w2*s[2] + bz;
    }
    const float a0 = wsh[31], a1 = wsh[32], a2 = wsh[33], ab = wsh[40];
    for (int i = tid; i < 34*64; i += 256){
      int r = i >> 6, x = i & 63;
      const float* s = sIN + (r+4)*75 + x + 4;
      sU1[r*65 + x] = a0*s[0] + a1*s[1] + a2*s[2] + ab;
    }
  }
  __syncthreads();

  const int oy  = tid >> 3;
  const int ox0 = (tid & 7) << 3;

  {
    const float w0 = wsh[3], w1 = wsh[4], w2 = wsh[5], bz = wsh[38];
    for (int i = tid; i < 40*72; i += 256){
      int r = i / 72, x = i - r*72;
      sT2[r*73 + x] = w0*sT1[r*73+x] + w1*sT1[(r+1)*73+x] + w2*sT1[(r+2)*73+x] + bz;
    }
    const float v0 = wsh[34], v1 = wsh[35], v2 = wsh[36], vb = wsh[41];
    float o8[8];
    #pragma unroll
    for (int j = 0; j < 8; j++){
      int ox = ox0 + j;
      o8[j] = v0*sU1[oy*65+ox] + v1*sU1[(oy+1)*65+ox] + v2*sU1[(oy+2)*65+ox] + vb;
    }
    uint4 u;
    u.x = pkbf(o8[0], o8[1]); u.y = pkbf(o8[2], o8[3]);
    u.z = pkbf(o8[4], o8[5]); u.w = pkbf(o8[6], o8[7]);
    *(uint4*)(x3out + (long long)b*out_bs + (long long)c*HW
              + (long long)(ty0+oy)*Wdim + tx0 + ox0) = u;
  }
  __syncthreads();

  {
    const float bz = wsh[39];
    float a[8];
    #pragma unroll
    for (int j = 0; j < 8; j++) a[j] = bz;
    #pragma unroll
    for (int ky = 0; ky < 5; ky++){
      const float* row = sT2 + (oy + 2*ky)*73 + ox0;
      float buf[16];
      #pragma unroll
      for (int i = 0; i < 16; i++) buf[i] = row[i];
      #pragma unroll
      for (int kx = 0; kx < 5; kx++){
        const float wv = wsh[6 + ky*5 + kx];
        #pragma unroll
        for (int j = 0; j < 8; j++) a[j] += wv * buf[kx*2 + j];
      }
    }
    uint4 u;
    u.x = pkbf(a[0], a[1]); u.y = pkbf(a[2], a[3]);
    u.z = pkbf(a[4], a[5]); u.w = pkbf(a[6], a[7]);
    *(uint4*)(l3pre + (long long)b*out_bs + (long long)c*HW
              + (long long)(ty0+oy)*Wdim + tx0 + ox0) = u;
  }
}

// ---------------------------------------------------------------------------
// Fused branch-2 depthwise chain: 32x64 output tile, bf16 I/O.
// ---------------------------------------------------------------------------
__global__ __launch_bounds__(256)
void branch2_kernel(const __nv_bfloat16* __restrict__ in, long long in_bs,
    const float* __restrict__ l5w1, const float* __restrict__ l5b1,
    const float* __restrict__ l5w2, const float* __restrict__ l5b2,
    const float* __restrict__ x5w,  const float* __restrict__ x5b,
    __nv_bfloat16* __restrict__ l5pre, __nv_bfloat16* __restrict__ x5out,
    long long out_bs)
{
  __shared__ float sIN[48*81];
  __shared__ float sV1[44*77];
  __shared__ float wsh[104];

  const int c = blockIdx.z & 63, b = blockIdx.z >> 6;
  const int ty0 = blockIdx.y * 32, tx0 = blockIdx.x * 64;
  const int tid = threadIdx.x;

  if (tid < 102){
    float v;
    if      (tid < 25) v = l5w1[c*25 + tid];
    else if (tid < 74) v = l5w2[c*49 + tid-25];
    else if (tid < 99) v = x5w[c*25 + tid-74];
    else if (tid == 99)  v = l5b1[c];
    else if (tid == 100) v = l5b2[c];
    else                 v = x5b[c];
    wsh[tid] = v;
  }

  const __nv_bfloat16* ip = in + (long long)b*in_bs + (long long)c*HW;
  for (int i = tid; i < 48*80; i += 256){
    int sy = i / 80, sx = i - sy*80;
    int gy = ty0 + sy - 8, gx = tx0 + sx - 8;
    float v = 0.f;
    if ((unsigned)gy < 128u && (unsigned)gx < 128u) v = __bfloat162float(ip[gy*Wdim + gx]);
    sIN[sy*81 + sx] = v;
  }
  __syncthreads();

  const int oy  = tid >> 3;
  const int ox0 = (tid & 7) << 3;

  {
    const float bz = wsh[99];
    for (int g = tid; g < 44*19; g += 256){
      int r = g / 19, c4 = (g - r*19) << 2;
      float a0 = bz, a1 = bz, a2 = bz, a3 = bz;
      #pragma unroll
      for (int ky = 0; ky < 5; ky++){
        const float* row = sIN + (r+ky)*81 + c4;
        float buf[8];
        #pragma unroll
        for (int i = 0; i < 8; i++) buf[i] = row[i];
        #pragma unroll
        for (int kx = 0; kx < 5; kx++){
          const float wv = wsh[ky*5+kx];
          a0 += wv*buf[kx+0];
          a1 += wv*buf[kx+1];
          a2 += wv*buf[kx+2];
          a3 += wv*buf[kx+3];
        }
      }
      float* d = sV1 + r*77 + c4;
      d[0]=a0; d[1]=a1; d[2]=a2; d[3]=a3;
    }
    const float xb = wsh[101];
    float a[8];
    #pragma unroll
    for (int j = 0; j < 8; j++) a[j] = xb;
    #pragma unroll
    for (int ky = 0; ky < 5; ky++){
      const float* row = sIN + (oy+6+ky)*81 + ox0 + 6;
      float buf[12];
      #pragma unroll
      for (int i = 0; i < 12; i++) buf[i] = row[i];
      #pragma unroll
      for (int kx = 0; kx < 5; kx++){
        const float wv = wsh[74 + ky*5 + kx];
        #pragma unroll
        for (int j = 0; j < 8; j++) a[j] += wv * buf[kx + j];
      }
    }
    uint4 u;
    u.x = pkbf(a[0], a[1]); u.y = pkbf(a[2], a[3]);
    u.z = pkbf(a[4], a[5]); u.w = pkbf(a[6], a[7]);
    *(uint4*)(x5out + (long long)b*out_bs + (long long)c*HW
              + (long long)(ty0+oy)*Wdim + tx0 + ox0) = u;
  }
  __syncthreads();

  {
    const float bz = wsh[100];
    float a[8];
    #pragma unroll
    for (int j = 0; j < 8; j++) a[j] = bz;
    #pragma unroll
    for (int ky = 0; ky < 7; ky++){
      const float* row = sV1 + (oy + 2*ky)*77 + ox0;
      float buf[20];
      #pragma unroll
      for (int i = 0; i < 20; i++) buf[i] = row[i];
      #pragma unroll
      for (int kx = 0; kx < 7; kx++){
        const float wv = wsh[25 + ky*7 + kx];
        #pragma unroll
        for (int j = 0; j < 8; j++) a[j] += wv * buf[kx*2 + j];
      }
    }
    uint4 u;
    u.x = pkbf(a[0], a[1]); u.y = pkbf(a[2], a[3]);
    u.z = pkbf(a[4], a[5]); u.w = pkbf(a[6], a[7]);
    *(uint4*)(l5pre + (long long)b*out_bs + (long long)c*HW
              + (long long)(ty0+oy)*Wdim + tx0 + ox0) = u;
  }
}

// ---------------------------------------------------------------------------
extern "C" void kernel_launch(void* const* d_in, const int* in_sizes, int n_in,
                              void* d_out, int out_size)
{
  const float* x    = (const float*)d_in[0];
  const float* ln_w = (const float*)d_in[1];
  const float* ln_b = (const float*)d_in[2];
  const float* scale= (const float*)d_in[3];
  const float* pf_w = (const float*)d_in[4];
  const float* pf_b = (const float*)d_in[5];
  const float* l3w1 = (const float*)d_in[6];
  const float* l3b1 = (const float*)d_in[7];
  const float* l3w2 = (const float*)d_in[8];
  const float* l3b2 = (const float*)d_in[9];
  const float* l3w3 = (const float*)d_in[10];
  const float* l3b3 = (const float*)d_in[11];
  const float* l3w4 = (const float*)d_in[12];
  const float* l3b4 = (const float*)d_in[13];
  const float* l5w1 = (const float*)d_in[14];
  const float* l5b1 = (const float*)d_in[15];
  const float* l5w2 = (const float*)d_in[16];
  const float* l5b2 = (const float*)d_in[17];
  const float* l5w3 = (const float*)d_in[18];
  const float* l5b3 = (const float*)d_in[19];
  const float* x3aw = (const float*)d_in[20];
  const float* x3ab = (const float*)d_in[21];
  const float* x3bw = (const float*)d_in[22];
  const float* x3bb = (const float*)d_in[23];
  const float* x5w  = (const float*)d_in[24];
  const float* x5b  = (const float*)d_in[25];
  const float* pl_w = (const float*)d_in[26];
  const float* pl_b = (const float*)d_in[27];
  float* out = (float*)d_out;

  __nv_bfloat16 *p_h, *p_t1, *p_x3, *p_at;
  cudaGetSymbolAddress((void**)&p_h,  g_h);
  cudaGetSymbolAddress((void**)&p_t1, g_t1);
  cudaGetSymbolAddress((void**)&p_x3, g_x3);
  cudaGetSymbolAddress((void**)&p_at, g_at);

  const long long BS_H = 256LL*HW, BS128 = 128LL*HW;
  dim3 gbr(2, 4, 16*64);
  const int NT = 4;
  dim3 gpf(32, 16, 2), g1(32, 16, 1);

  const int SM_PF   = 128*132*4 + 2*128*PX*4 + 4096;          // 210944
  const int SM_ATTN = 128*68*2  + 2*128*PX*2 + 4*128*PX*2;    // 226304
  const int SM_PL   = 128*132*2 + 2*128*PX*2;                 // 103424

  // 1) LN + pf expand (128 -> 256), out bf16
  {
    auto k = pw_mma<true,false,0,float,__nv_bfloat16,float,false>;
    cudaFuncSetAttribute((const void*)k, cudaFuncAttributeMaxDynamicSharedMemorySize, SM_PF);
    k<<<gpf,256,SM_PF>>>(x, BS128, ln_w, ln_b, pf_w, nullptr, pf_b, nullptr,
                         nullptr,0, nullptr,0, nullptr, nullptr,
                         p_h, BS_H, NT);
  }
  // 2) fused dw branches (bf16 I/O)
  branch1_kernel<<<gbr,256>>>(p_h, BS_H, l3w1,l3b1, l3w2,l3b2, l3w3,l3b3,
                              x3aw,x3ab, x3bw,x3bb, p_t1, p_x3, BS128);
  branch2_kernel<<<gbr,256>>>(p_h + 64LL*HW, BS_H, l5w1,l5b1, l5w2,l5b2,
                              x5w,x5b, p_t1 + 64LL*HW, p_x3 + 64LL*HW, BS128);
  // 3) t = ( blockdiag(l3w4,l5w3) @ [l3pre;l5pre] + bias ) * gate * xh  (all pipelined)
  {
    auto k = pw_mma<false,true,1,__nv_bfloat16,__nv_bfloat16,__nv_bfloat16,true>;
    cudaFuncSetAttribute((const void*)k, cudaFuncAttributeMaxDynamicSharedMemorySize, SM_ATTN);
    k<<<g1,256,SM_ATTN>>>(p_t1, BS128, nullptr, nullptr, l3w4, l5w3,
                          l3b4, l5b3, p_x3, BS128, p_h + 128LL*HW, BS_H,
                          nullptr, nullptr, p_at, BS128, NT);
  }
  // 4) final: pl(t) * scale + x  (fp32 out)
  {
    auto k = pw_mma<false,false,2,__nv_bfloat16,float,__nv_bfloat16,false>;
    cudaFuncSetAttribute((const void*)k, cudaFuncAttributeMaxDynamicSharedMemorySize, SM_PL);
    k<<<g1,256,SM_PL>>>(p_at, BS128, nullptr, nullptr, pl_w, nullptr,
                        pl_b, nullptr, nullptr,0, nullptr,0,
                        scale, x, out, BS128, NT);
  }
}

// round 7
// speedup vs baseline: 1.8510x; 1.0129x over previous
#include <cuda_runtime.h>
#include <cuda_bf16.h>
#include <cstdint>

#define HW   16384
#define Wdim 128

// ---------------- scratch (bf16 intermediates) ----------------
__device__ __nv_bfloat16 g_h [16ULL*256*16384];  // pf out: a(0..127) | xh(128..255)
__device__ __nv_bfloat16 g_t1[16ULL*128*16384];  // l3pre(0..63) | l5pre(64..127)
__device__ __nv_bfloat16 g_x3[16ULL*128*16384];  // x3out(0..63) | x5(64..127)

// ---------------- helpers ----------------
__device__ __forceinline__ uint32_t smem_u32(const void* p){
  uint32_t a;
  asm("{ .reg .u64 t; cvta.to.shared.u64 t, %1; cvt.u32.u64 %0, t; }" : "=r"(a) : "l"(p));
  return a;
}
__device__ __forceinline__ void cp16(uint32_t s, const void* g){
  asm volatile("cp.async.cg.shared.global [%0], [%1], 16;" :: "r"(s), "l"(g) : "memory");
}
__device__ __forceinline__ void cp_commit(){ asm volatile("cp.async.commit_group;" ::: "memory"); }
__device__ __forceinline__ void cp_wait0(){ asm volatile("cp.async.wait_group 0;" ::: "memory"); }
__device__ __forceinline__ void cp_wait1(){ asm volatile("cp.async.wait_group 1;" ::: "memory"); }
__device__ __forceinline__ void mma_tf32(float* d, const uint32_t* a, const uint32_t* b){
  asm volatile(
    "mma.sync.aligned.m16n8k8.row.col.f32.tf32.tf32.f32 "
    "{%0,%1,%2,%3}, {%4,%5,%6,%7}, {%8,%9}, {%0,%1,%2,%3};"
    : "+f"(d[0]), "+f"(d[1]), "+f"(d[2]), "+f"(d[3])
    : "r"(a[0]), "r"(a[1]), "r"(a[2]), "r"(a[3]), "r"(b[0]), "r"(b[1]));
}
__device__ __forceinline__ uint32_t pkbf(float a, float b){
  __nv_bfloat162 t = __floats2bfloat162_rn(a, b);
  return *reinterpret_cast<uint32_t*>(&t);
}
__device__ __forceinline__ float bf2f(__nv_bfloat16 v){ return __bfloat162float(v); }

// ---------------------------------------------------------------------------
// pf: LN + 1x1 expand (128 -> 256), tf32 mma, 512 threads, cp.async pipeline.
// out bf16. blockIdx.z = mt (which 128 of the 256 output channels).
// ---------------------------------------------------------------------------
#define PXF 136
__global__ __launch_bounds__(512, 1)
void pf_kernel(const float* __restrict__ in,
               const float* __restrict__ lnw, const float* __restrict__ lnb,
               const float* __restrict__ w, const float* __restrict__ bias,
               __nv_bfloat16* __restrict__ out, int ntiles)
{
  extern __shared__ char smc[];
  float* Ws  = (float*)smc;                         // 128 x 132 f32
  float* Xb0 = (float*)(smc + 67584);
  float* Xb1 = (float*)(smc + 67584 + 69632);
  float* sLNw  = (float*)(smc + 206848);
  float* sLNb  = (float*)(smc + 207360);
  float* sMu   = (float*)(smc + 207872);
  float* sRs   = (float*)(smc + 208384);
  float* sPart = (float*)(smc + 208896);            // 1024 f32
  const uint32_t sbase = smem_u32(smc);
  const uint32_t xu0 = sbase + 67584, xu1 = xu0 + 69632;

  const int tid = threadIdx.x;
  const int wid = tid >> 5, lid = tid & 31;
  const int b   = blockIdx.y;
  const int mt  = blockIdx.z;

  const float* wp = w + (size_t)mt*128*128;
  for (int i = tid; i < 128*32; i += 512){
    int oc = i >> 5, c4 = (i & 31) << 2;
    *(float4*)(Ws + oc*132 + c4) = *(const float4*)(wp + oc*128 + c4);
  }
  if (tid < 128){ sLNw[tid] = lnw[tid]; sLNb[tid] = lnb[tid]; }

  const int wm = wid & 7, wn = wid >> 3;
  const int oc0 = wm*16, pxw = wn*64;
  const int r = lid >> 2, cq = lid & 3;
  const int oA = oc0 + r, oB = oc0 + r + 8;
  const float bzA = bias[mt*128 + oA], bzB = bias[mt*128 + oB];

  auto stage = [&](int t){
    const int px0 = (blockIdx.x * ntiles + t) * 128;
    const uint32_t xb = (t & 1) ? xu1 : xu0;
    const float* ipx = in + (size_t)b*(128LL*HW) + px0;
    #pragma unroll 4
    for (int i = tid; i < 128*32; i += 512){
      int ic = i >> 5, pc = (i & 31) << 2;
      cp16(xb + (uint32_t)(ic*PXF + pc)*4u, ipx + (size_t)ic*HW + pc);
    }
    cp_commit();
  };
  stage(0);

  for (int t = 0; t < ntiles; t++){
    if (t+1 < ntiles){ stage(t+1); cp_wait1(); }
    else             { cp_wait0(); }
    __syncthreads();
    float* Xs = (t & 1) ? Xb1 : Xb0;
    const int px0 = (blockIdx.x * ntiles + t) * 128;

    // LN stats: 512 threads, 4 quarters per pixel
    {
      const int px = tid & 127, q = tid >> 7;
      float s = 0.f, s2 = 0.f;
      #pragma unroll 8
      for (int ic = 0; ic < 32; ic++){
        float v = Xs[(q*32 + ic)*PXF + px]; s += v; s2 += v*v;
      }
      sPart[tid] = s; sPart[512 + tid] = s2;
    }
    __syncthreads();
    if (tid < 128){
      float ss = sPart[tid] + sPart[tid+128] + sPart[tid+256] + sPart[tid+384];
      float qq = sPart[512+tid] + sPart[640+tid] + sPart[768+tid] + sPart[896+tid];
      float mu = ss * (1.f/128.f);
      sMu[tid] = mu;
      sRs[tid] = rsqrtf(qq*(1.f/128.f) - mu*mu + 1e-6f);
    }
    __syncthreads();

    float muv[8], rsv[8];
    #pragma unroll
    for (int ni = 0; ni < 8; ni++){
      int px = pxw + ni*8 + r;
      muv[ni] = sMu[px]; rsv[ni] = sRs[px];
    }

    float acc[8][4];
    #pragma unroll
    for (int ni = 0; ni < 8; ni++)
      #pragma unroll
      for (int j = 0; j < 4; j++) acc[ni][j] = 0.f;

    #pragma unroll 2
    for (int ks = 0; ks < 16; ks++){
      const int k0 = ks * 8;
      uint32_t af[4];
      {
        const float* ab = Ws + (oc0 + r)*132 + k0 + cq;
        af[0] = __float_as_uint(ab[0]);
        af[1] = __float_as_uint(ab[8*132]);
        af[2] = __float_as_uint(ab[4]);
        af[3] = __float_as_uint(ab[8*132 + 4]);
      }
      const int kb = k0 + cq;
      const float w0 = sLNw[kb], bb0 = sLNb[kb];
      const float w4 = sLNw[kb+4], bb4 = sLNb[kb+4];
      uint32_t bf[8][2];
      #pragma unroll
      for (int ni = 0; ni < 8; ni++){
        const float* bb = Xs + kb*PXF + pxw + ni*8 + r;
        float x0 = bb[0], x4 = bb[4*PXF];
        x0 = (x0 - muv[ni]) * (w0 * rsv[ni]) + bb0;
        x4 = (x4 - muv[ni]) * (w4 * rsv[ni]) + bb4;
        bf[ni][0] = __float_as_uint(x0);
        bf[ni][1] = __float_as_uint(x4);
      }
      #pragma unroll
      for (int ni = 0; ni < 8; ni++)
        mma_tf32(acc[ni], af, bf[ni]);
    }

    __nv_bfloat16* opA = out + ((size_t)b*256 + mt*128 + oA)*HW + px0 + pxw + cq*2;
    __nv_bfloat16* opB = out + ((size_t)b*256 + mt*128 + oB)*HW + px0 + pxw + cq*2;
    #pragma unroll
    for (int ni = 0; ni < 8; ni++){
      *(uint32_t*)(opA + ni*8) = pkbf(acc[ni][0] + bzA, acc[ni][1] + bzA);
      *(uint32_t*)(opB + ni*8) = pkbf(acc[ni][2] + bzB, acc[ni][3] + bzB);
    }
    __syncthreads();
  }
}

// ---------------------------------------------------------------------------
// fuse2: attn + pl in one kernel, 64-px tiles, 512 threads.
//   GEMM1: t = (blockdiag(l3w4,l5w3) @ pre + b1) * gate * xh  -> smem (bf16)
//   GEMM2: out = (pl_w @ t + pl_b) * scale + x                -> gmem (f32)
// ---------------------------------------------------------------------------
#define PT 72
#define F2_W1   0
#define F2_W2   18432
#define F2_PRE  53248
#define F2_GATE 90112
#define F2_XH   126976
#define F2_T    163840
#define F2_TOT  182272
#define TBUF    18432

__global__ __launch_bounds__(512, 1)
void fuse2_kernel(const __nv_bfloat16* __restrict__ pre,
                  const __nv_bfloat16* __restrict__ gate,
                  const __nv_bfloat16* __restrict__ xh, long long xh_bs,
                  const float* __restrict__ w1A, const float* __restrict__ w1B,
                  const float* __restrict__ b1A, const float* __restrict__ b1B,
                  const float* __restrict__ plw, const float* __restrict__ plb,
                  const float* __restrict__ scal, const float* __restrict__ xres,
                  float* __restrict__ out, int ntiles)
{
  extern __shared__ char smc[];
  __nv_bfloat16* W1s = (__nv_bfloat16*)(smc + F2_W1);    // 128 x 64 compact, pitch 72
  __nv_bfloat16* W2s = (__nv_bfloat16*)(smc + F2_W2);    // 128 x 128, pitch 136
  __nv_bfloat16* Ts  = (__nv_bfloat16*)(smc + F2_T);     // 128 x 64, pitch 72
  const uint32_t sbase = smem_u32(smc);

  const int tid = threadIdx.x;
  const int wid = tid >> 5, lid = tid & 31;
  const int b   = blockIdx.y;

  // stage W1 (compact blockdiag) and W2 (pl_w), f32 -> bf16
  for (int i = tid; i < 128*16; i += 512){
    int oc = i >> 4, k4 = (i & 15) << 2;
    float4 v = (oc < 64) ? *(const float4*)(w1A + oc*64 + k4)
                         : *(const float4*)(w1B + (oc-64)*64 + k4);
    uint32_t* d = (uint32_t*)(W1s + oc*PT + k4);
    d[0] = pkbf(v.x, v.y); d[1] = pkbf(v.z, v.w);
  }
  for (int i = tid; i < 128*32; i += 512){
    int oc = i >> 5, c4 = (i & 31) << 2;
    float4 v = *(const float4*)(plw + oc*128 + c4);
    uint32_t* d = (uint32_t*)(W2s + oc*136 + c4);
    d[0] = pkbf(v.x, v.y); d[1] = pkbf(v.z, v.w);
  }

  const int wm = wid & 7, wn = wid >> 3;
  const int oc0 = wm*16, pxw = wn*32;
  const int r = lid >> 2, cq = lid & 3;
  const int oA = oc0 + r, oB = oc0 + r + 8;
  const int koff = (oc0 >= 64) ? 64 : 0;

  const float bz1A = (oA < 64) ? b1A[oA] : b1B[oA-64];
  const float bz1B = (oB < 64) ? b1A[oB] : b1B[oB-64];
  const float bz2A = plb[oA], bz2B = plb[oB];
  const float scA  = scal[oA], scB = scal[oB];

  auto stage = [&](int t){
    const int px0 = (blockIdx.x * ntiles + t) * 64;
    const uint32_t buf = (uint32_t)(t & 1) * TBUF;
    const __nv_bfloat16* p1 = pre  + (size_t)b*(128LL*HW) + px0;
    const __nv_bfloat16* p2 = gate + (size_t)b*(128LL*HW) + px0;
    const __nv_bfloat16* p3 = xh   + (size_t)b*xh_bs      + px0;
    #pragma unroll 2
    for (int i = tid; i < 128*8; i += 512){
      int ic = i >> 3, pc = (i & 7) << 3;
      uint32_t off = (uint32_t)(ic*PT + pc)*2u;
      cp16(sbase + F2_PRE  + buf + off, p1 + (size_t)ic*HW + pc);
      cp16(sbase + F2_GATE + buf + off, p2 + (size_t)ic*HW + pc);
      cp16(sbase + F2_XH   + buf + off, p3 + (size_t)ic*HW + pc);
    }
    cp_commit();
  };
  stage(0);

  for (int t = 0; t < ntiles; t++){
    if (t+1 < ntiles){ stage(t+1); cp_wait1(); }
    else             { cp_wait0(); }
    __syncthreads();
    const int buf = (t & 1);
    const __nv_bfloat16* Ps = (const __nv_bfloat16*)(smc + F2_PRE  + buf*TBUF);
    const __nv_bfloat16* Gs = (const __nv_bfloat16*)(smc + F2_GATE + buf*TBUF);
    const __nv_bfloat16* Hs = (const __nv_bfloat16*)(smc + F2_XH   + buf*TBUF);
    const int px0 = (blockIdx.x * ntiles + t) * 64;

    // ---- GEMM1: K=64 (this warp's diag block) ----
    float a1[4][4];
    #pragma unroll
    for (int ni = 0; ni < 4; ni++)
      #pragma unroll
      for (int j = 0; j < 4; j++) a1[ni][j] = 0.f;

    #pragma unroll
    for (int ks = 0; ks < 8; ks++){
      const int k0 = ks * 8;
      uint32_t af[4];
      {
        const __nv_bfloat16* ab = W1s + (oc0 + r)*PT + k0 + cq;
        af[0] = __float_as_uint(bf2f(ab[0]));
        af[1] = __float_as_uint(bf2f(ab[8*PT]));
        af[2] = __float_as_uint(bf2f(ab[4]));
        af[3] = __float_as_uint(bf2f(ab[8*PT + 4]));
      }
      uint32_t bf[4][2];
      #pragma unroll
      for (int ni = 0; ni < 4; ni++){
        const __nv_bfloat16* bb = Ps + (koff + k0 + cq)*PT + pxw + ni*8 + r;
        bf[ni][0] = __float_as_uint(bf2f(bb[0]));
        bf[ni][1] = __float_as_uint(bf2f(bb[4*PT]));
      }
      #pragma unroll
      for (int ni = 0; ni < 4; ni++)
        mma_tf32(a1[ni], af, bf[ni]);
    }

    // epilogue1: t = (acc + b1) * gate * xh -> Ts (bf16)
    #pragma unroll
    for (int ni = 0; ni < 4; ni++){
      const int pxl = pxw + ni*8 + cq*2;
      float2 gA = __bfloat1622float2(*(const __nv_bfloat162*)(Gs + oA*PT + pxl));
      float2 hA = __bfloat1622float2(*(const __nv_bfloat162*)(Hs + oA*PT + pxl));
      *(uint32_t*)(Ts + oA*PT + pxl) =
        pkbf((a1[ni][0] + bz1A)*gA.x*hA.x, (a1[ni][1] + bz1A)*gA.y*hA.y);
      float2 gB = __bfloat1622float2(*(const __nv_bfloat162*)(Gs + oB*PT + pxl));
      float2 hB = __bfloat1622float2(*(const __nv_bfloat162*)(Hs + oB*PT + pxl));
      *(uint32_t*)(Ts + oB*PT + pxl) =
        pkbf((a1[ni][2] + bz1B)*gB.x*hB.x, (a1[ni][3] + bz1B)*gB.y*hB.y);
    }
    __syncthreads();

    // ---- GEMM2: out = plw @ t, K=128 ----
    float a2[4][4];
    #pragma unroll
    for (int ni = 0; ni < 4; ni++)
      #pragma unroll
      for (int j = 0; j < 4; j++) a2[ni][j] = 0.f;

    #pragma unroll 2
    for (int ks = 0; ks < 16; ks++){
      const int k0 = ks * 8;
      uint32_t af[4];
      {
        const __nv_bfloat16* ab = W2s + (oc0 + r)*136 + k0 + cq;
        af[0] = __float_as_uint(bf2f(ab[0]));
        af[1] = __float_as_uint(bf2f(ab[8*136]));
        af[2] = __float_as_uint(bf2f(ab[4]));
        af[3] = __float_as_uint(bf2f(ab[8*136 + 4]));
      }
      uint32_t bf[4][2];
      #pragma unroll
      for (int ni = 0; ni < 4; ni++){
        const __nv_bfloat16* bb = Ts + (k0 + cq)*PT + pxw + ni*8 + r;
        bf[ni][0] = __float_as_uint(bf2f(bb[0]));
        bf[ni][1] = __float_as_uint(bf2f(bb[4*PT]));
      }
      #pragma unroll
      for (int ni = 0; ni < 4; ni++)
        mma_tf32(a2[ni], af, bf[ni]);
    }

    // epilogue2: (acc + plb) * scale + x -> f32 out
    {
      const int pc = px0 + pxw + cq*2;
      float* opA = out + ((size_t)b*128 + oA)*HW + pc;
      float* opB = out + ((size_t)b*128 + oB)*HW + pc;
      const float* shA = xres + ((size_t)b*128 + oA)*HW + pc;
      const float* shB = xres + ((size_t)b*128 + oB)*HW + pc;
      #pragma unroll
      for (int ni = 0; ni < 4; ni++){
        float2 sA = *(const float2*)(shA + ni*8);
        float2 sB = *(const float2*)(shB + ni*8);
        *(float2*)(opA + ni*8) = make_float2((a2[ni][0] + bz2A)*scA + sA.x,
                                             (a2[ni][1] + bz2A)*scA + sA.y);
        *(float2*)(opB + ni*8) = make_float2((a2[ni][2] + bz2B)*scB + sB.x,
                                             (a2[ni][3] + bz2B)*scB + sB.y);
      }
    }
    __syncthreads();
  }
}

// ---------------------------------------------------------------------------
// Fused branch-1 depthwise chain: 32x64 output tile, bf16 I/O. (unchanged)
// ---------------------------------------------------------------------------
__global__ __launch_bounds__(256)
void branch1_kernel(const __nv_bfloat16* __restrict__ in, long long in_bs,
    const float* __restrict__ l3w1, const float* __restrict__ l3b1,
    const float* __restrict__ l3w2, const float* __restrict__ l3b2,
    const float* __restrict__ l3w3, const float* __restrict__ l3b3,
    const float* __restrict__ x3aw, const float* __restrict__ x3ab,
    const float* __restrict__ x3bw, const float* __restrict__ x3bb,
    __nv_bfloat16* __restrict__ l3pre, __nv_bfloat16* __restrict__ x3out,
    long long out_bs)
{
  __shared__ float sIN[42*75];
  __shared__ float sT1[42*73];
  __shared__ float sU1[34*65];
  __shared__ float sT2[40*73];
  __shared__ float wsh[42];

  const int c = blockIdx.z & 63, b = blockIdx.z >> 6;
  const int ty0 = blockIdx.y * 32, tx0 = blockIdx.x * 64;
  const int tid = threadIdx.x;

  if (tid < 42){
    float v;
    if      (tid < 3)  v = l3w1[c*3 + tid];
    else if (tid < 6)  v = l3w2[c*3 + tid-3];
    else if (tid < 31) v = l3w3[c*25 + tid-6];
    else if (tid < 34) v = x3aw[c*3 + tid-31];
    else if (tid < 37) v = x3bw[c*3 + tid-34];
    else if (tid == 37) v = l3b1[c];
    else if (tid == 38) v = l3b2[c];
    else if (tid == 39) v = l3b3[c];
    else if (tid == 40) v = x3ab[c];
    else                v = x3bb[c];
    wsh[tid] = v;
  }

  const __nv_bfloat16* ip = in + (long long)b*in_bs + (long long)c*HW;
  for (int i = tid; i < 42*74; i += 256){
    int sy = i / 74, sx = i - sy*74;
    int gy = ty0 + sy - 5, gx = tx0 + sx - 5;
    float v = 0.f;
    if ((unsigned)gy < 128u && (unsigned)gx < 128u) v = __bfloat162float(ip[gy*Wdim + gx]);
    sIN[sy*75 + sx] = v;
  }
  __syncthreads();

  {
    const float w0 = wsh[0], w1 = wsh[1], w2 = wsh[2], bz = wsh[37];
    for (int i = tid; i < 42*72; i += 256){
      int r = i / 72, x = i - r*72;
      const float* s = sIN + r*75 + x;
      sT1[r*73 + x] = w0*s[0] + w1*s[1] + w2*s[2] + bz;
    }
    const float a0 = wsh[31], a1 = wsh[32], a2 = wsh[33], ab = wsh[40];
    for (int i = tid; i < 34*64; i += 256){
      int r = i >> 6, x = i & 63;
      const float* s = sIN + (r+4)*75 + x + 4;
      sU1[r*65 + x] = a0*s[0] + a1*s[1] + a2*s[2] + ab;
    }
  }
  __syncthreads();

  const int oy  = tid >> 3;
  const int ox0 = (tid & 7) << 3;

  {
    const float w0 = wsh[3], w1 = wsh[4], w2 = wsh[5], bz = wsh[38];
    for (int i = tid; i < 40*72; i += 256){
      int r = i / 72, x = i - r*72;
      sT2[r*73 + x] = w0*sT1[r*73+x] + w1*sT1[(r+1)*73+x] + w2*sT1[(r+2)*73+x] + bz;
    }
    const float v0 = wsh[34], v1 = wsh[35], v2 = wsh[36], vb = wsh[41];
    float o8[8];
    #pragma unroll
    for (int j = 0; j < 8; j++){
      int ox = ox0 + j;
      o8[j] = v0*sU1[oy*65+ox] + v1*sU1[(oy+1)*65+ox] + v2*sU1[(oy+2)*65+ox] + vb;
    }
    uint4 u;
    u.x = pkbf(o8[0], o8[1]); u.y = pkbf(o8[2], o8[3]);
    u.z = pkbf(o8[4], o8[5]); u.w = pkbf(o8[6], o8[7]);
    *(uint4*)(x3out + (long long)b*out_bs + (long long)c*HW
              + (long long)(ty0+oy)*Wdim + tx0 + ox0) = u;
  }
  __syncthreads();

  {
    const float bz = wsh[39];
    float a[8];
    #pragma unroll
    for (int j = 0; j < 8; j++) a[j] = bz;
    #pragma unroll
    for (int ky = 0; ky < 5; ky++){
      const float* row = sT2 + (oy + 2*ky)*73 + ox0;
      float buf[16];
      #pragma unroll
      for (int i = 0; i < 16; i++) buf[i] = row[i];
      #pragma unroll
      for (int kx = 0; kx < 5; kx++){
        const float wv = wsh[6 + ky*5 + kx];
        #pragma unroll
        for (int j = 0; j < 8; j++) a[j] += wv * buf[kx*2 + j];
      }
    }
    uint4 u;
    u.x = pkbf(a[0], a[1]); u.y = pkbf(a[2], a[3]);
    u.z = pkbf(a[4], a[5]); u.w = pkbf(a[6], a[7]);
    *(uint4*)(l3pre + (long long)b*out_bs + (long long)c*HW
              + (long long)(ty0+oy)*Wdim + tx0 + ox0) = u;
  }
}

// ---------------------------------------------------------------------------
// Fused branch-2 depthwise chain: 32x64 output tile, bf16 I/O. (unchanged)
// ---------------------------------------------------------------------------
__global__ __launch_bounds__(256)
void branch2_kernel(const __nv_bfloat16* __restrict__ in, long long in_bs,
    const float* __restrict__ l5w1, const float* __restrict__ l5b1,
    const float* __restrict__ l5w2, const float* __restrict__ l5b2,
    const float* __restrict__ x5w,  const float* __restrict__ x5b,
    __nv_bfloat16* __restrict__ l5pre, __nv_bfloat16* __restrict__ x5out,
    long long out_bs)
{
  __shared__ float sIN[48*81];
  __shared__ float sV1[44*77];
  __shared__ float wsh[104];

  const int c = blockIdx.z & 63, b = blockIdx.z >> 6;
  const int ty0 = blockIdx.y * 32, tx0 = blockIdx.x * 64;
  const int tid = threadIdx.x;

  if (tid < 102){
    float v;
    if      (tid < 25) v = l5w1[c*25 + tid];
    else if (tid < 74) v = l5w2[c*49 + tid-25];
    else if (tid < 99) v = x5w[c*25 + tid-74];
    else if (tid == 99)  v = l5b1[c];
    else if (tid == 100) v = l5b2[c];
    else                 v = x5b[c];
    wsh[tid] = v;
  }

  const __nv_bfloat16* ip = in + (long long)b*in_bs + (long long)c*HW;
  for (int i = tid; i < 48*80; i += 256){
    int sy = i / 80, sx = i - sy*80;
    int gy = ty0 + sy - 8, gx = tx0 + sx - 8;
    float v = 0.f;
    if ((unsigned)gy < 128u && (unsigned)gx < 128u) v = __bfloat162float(ip[gy*Wdim + gx]);
    sIN[sy*81 + sx] = v;
  }
  __syncthreads();

  const int oy  = tid >> 3;
  const int ox0 = (tid & 7) << 3;

  {
    const float bz = wsh[99];
    for (int g = tid; g < 44*19; g += 256){
      int r = g / 19, c4 = (g - r*19) << 2;
      float a0 = bz, a1 = bz, a2 = bz, a3 = bz;
      #pragma unroll
      for (int ky = 0; ky < 5; ky++){
        const float* row = sIN + (r+ky)*81 + c4;
        float buf[8];
        #pragma unroll
        for (int i = 0; i < 8; i++) buf[i] = row[i];
        #pragma unroll
        for (int kx = 0; kx < 5; kx++){
          const float wv = wsh[ky*5+kx];
          a0 += wv*buf[kx+0];
          a1 += wv*buf[kx+1];
          a2 += wv*buf[kx+2];
          a3 += wv*buf[kx+3];
        }
      }
      float* d = sV1 + r*77 + c4;
      d[0]=a0; d[1]=a1; d[2]=a2; d[3]=a3;
    }
    const float xb = wsh[101];
    float a[8];
    #pragma unroll
    for (int j = 0; j < 8; j++) a[j] = xb;
    #pragma unroll
    for (int ky = 0; ky < 5; ky++){
      const float* row = sIN + (oy+6+ky)*81 + ox0 + 6;
      float buf[12];
      #pragma unroll
      for (int i = 0; i < 12; i++) buf[i] = row[i];
      #pragma unroll
      for (int kx = 0; kx < 5; kx++){
        const float wv = wsh[74 + ky*5 + kx];
        #pragma unroll
        for (int j = 0; j < 8; j++) a[j] += wv * buf[kx + j];
      }
    }
    uint4 u;
    u.x = pkbf(a[0], a[1]); u.y = pkbf(a[2], a[3]);
    u.z = pkbf(a[4], a[5]); u.w = pkbf(a[6], a[7]);
    *(uint4*)(x5out + (long long)b*out_bs + (long long)c*HW
              + (long long)(ty0+oy)*Wdim + tx0 + ox0) = u;
  }
  __syncthreads();

  {
    const float bz = wsh[100];
    float a[8];
    #pragma unroll
    for (int j = 0; j < 8; j++) a[j] = bz;
    #pragma unroll
    for (int ky = 0; ky < 7; ky++){
      const float* row = sV1 + (oy + 2*ky)*77 + ox0;
      float buf[20];
      #pragma unroll
      for (int i = 0; i < 20; i++) buf[i] = row[i];
      #pragma unroll
      for (int kx = 0; kx < 7; kx++){
        const float wv = wsh[25 + ky*7 + kx];
        #pragma unroll
        for (int j = 0; j < 8; j++) a[j] += wv * buf[kx*2 + j];
      }
    }
    uint4 u;
    u.x = pkbf(a[0], a[1]); u.y = pkbf(a[2], a[3]);
    u.z = pkbf(a[4], a[5]); u.w = pkbf(a[6], a[7]);
    *(uint4*)(l5pre + (long long)b*out_bs + (long long)c*HW
              + (long long)(ty0+oy)*Wdim + tx0 + ox0) = u;
  }
}

// ---------------------------------------------------------------------------
extern "C" void kernel_launch(void* const* d_in, const int* in_sizes, int n_in,
                              void* d_out, int out_size)
{
  const float* x    = (const float*)d_in[0];
  const float* ln_w = (const float*)d_in[1];
  const float* ln_b = (const float*)d_in[2];
  const float* scale= (const float*)d_in[3];
  const float* pf_w = (const float*)d_in[4];
  const float* pf_b = (const float*)d_in[5];
  const float* l3w1 = (const float*)d_in[6];
  const float* l3b1 = (const float*)d_in[7];
  const float* l3w2 = (const float*)d_in[8];
  const float* l3b2 = (const float*)d_in[9];
  const float* l3w3 = (const float*)d_in[10];
  const float* l3b3 = (const float*)d_in[11];
  const float* l3w4 = (const float*)d_in[12];
  const float* l3b4 = (const float*)d_in[13];
  const float* l5w1 = (const float*)d_in[14];
  const float* l5b1 = (const float*)d_in[15];
  const float* l5w2 = (const float*)d_in[16];
  const float* l5b2 = (const float*)d_in[17];
  const float* l5w3 = (const float*)d_in[18];
  const float* l5b3 = (const float*)d_in[19];
  const float* x3aw = (const float*)d_in[20];
  const float* x3ab = (const float*)d_in[21];
  const float* x3bw = (const float*)d_in[22];
  const float* x3bb = (const float*)d_in[23];
  const float* x5w  = (const float*)d_in[24];
  const float* x5b  = (const float*)d_in[25];
  const float* pl_w = (const float*)d_in[26];
  const float* pl_b = (const float*)d_in[27];
  float* out = (float*)d_out;

  __nv_bfloat16 *p_h, *p_t1, *p_x3;
  cudaGetSymbolAddress((void**)&p_h,  g_h);
  cudaGetSymbolAddress((void**)&p_t1, g_t1);
  cudaGetSymbolAddress((void**)&p_x3, g_x3);

  const long long BS_H = 256LL*HW, BS128 = 128LL*HW;
  dim3 gbr(2, 4, 16*64);

  // 1) LN + pf expand (128 -> 256), 512 threads
  {
    const int SM_PF = 212992;
    cudaFuncSetAttribute((const void*)pf_kernel, cudaFuncAttributeMaxDynamicSharedMemorySize, SM_PF);
    pf_kernel<<<dim3(32,16,2),512,SM_PF>>>(x, ln_w, ln_b, pf_w, pf_b, p_h, 4);
  }
  // 2) fused dw branches (bf16 I/O)
  branch1_kernel<<<gbr,256>>>(p_h, BS_H, l3w1,l3b1, l3w2,l3b2, l3w3,l3b3,
                              x3aw,x3ab, x3bw,x3bb, p_t1, p_x3, BS128);
  branch2_kernel<<<gbr,256>>>(p_h + 64LL*HW, BS_H, l5w1,l5b1, l5w2,l5b2,
                              x5w,x5b, p_t1 + 64LL*HW, p_x3 + 64LL*HW, BS128);
  // 3+4) fused attn+pl, 512 threads
  {
    cudaFuncSetAttribute((const void*)fuse2_kernel, cudaFuncAttributeMaxDynamicSharedMemorySize, F2_TOT);
    fuse2_kernel<<<dim3(64,16),512,F2_TOT>>>(p_t1, p_x3, p_h + 128LL*HW, BS_H,
                                             l3w4, l5w3, l3b4, l5b3,
                                             pl_w, pl_b, scale, x, out, 4);
  }
}

// round 8
// speedup vs baseline: 2.2418x; 1.2111x over previous
#include <cuda_runtime.h>
#include <cuda_bf16.h>
#include <cstdint>

#define HW   16384
#define Wdim 128

// ---------------- scratch (bf16 intermediates) ----------------
__device__ __nv_bfloat16 g_h [16ULL*256*16384];  // pf out: a(0..127) | xh(128..255)
__device__ __nv_bfloat16 g_t1[16ULL*128*16384];  // l3pre(0..63) | l5pre(64..127)
__device__ __nv_bfloat16 g_x3[16ULL*128*16384];  // x3out(0..63) | x5(64..127)

// ---------------- helpers ----------------
__device__ __forceinline__ uint32_t smem_u32(const void* p){
  uint32_t a;
  asm("{ .reg .u64 t; cvta.to.shared.u64 t, %1; cvt.u32.u64 %0, t; }" : "=r"(a) : "l"(p));
  return a;
}
__device__ __forceinline__ void cp16(uint32_t s, const void* g){
  asm volatile("cp.async.cg.shared.global [%0], [%1], 16;" :: "r"(s), "l"(g) : "memory");
}
__device__ __forceinline__ void cp_commit(){ asm volatile("cp.async.commit_group;" ::: "memory"); }
__device__ __forceinline__ void cp_wait0(){ asm volatile("cp.async.wait_group 0;" ::: "memory"); }
__device__ __forceinline__ void cp_wait1(){ asm volatile("cp.async.wait_group 1;" ::: "memory"); }
__device__ __forceinline__ void mma_bf16(float* d, const uint32_t* a, const uint32_t* b){
  asm volatile(
    "mma.sync.aligned.m16n8k16.row.col.f32.bf16.bf16.f32 "
    "{%0,%1,%2,%3}, {%4,%5,%6,%7}, {%8,%9}, {%0,%1,%2,%3};"
    : "+f"(d[0]), "+f"(d[1]), "+f"(d[2]), "+f"(d[3])
    : "r"(a[0]), "r"(a[1]), "r"(a[2]), "r"(a[3]), "r"(b[0]), "r"(b[1]));
}
__device__ __forceinline__ uint32_t pkbf(float a, float b){
  __nv_bfloat162 t = __floats2bfloat162_rn(a, b);
  return *reinterpret_cast<uint32_t*>(&t);
}
// pack two bf16 separated by `stride` elements into one .b32 (lo,hi)
__device__ __forceinline__ uint32_t pk2u16(const __nv_bfloat16* p, int stride){
  uint16_t lo = *(const uint16_t*)p;
  uint16_t hi = *(const uint16_t*)(p + stride);
  return (uint32_t)lo | ((uint32_t)hi << 16);
}
__device__ __forceinline__ float2 ldbf2(const __nv_bfloat16* p){
  return __bfloat1622float2(*(const __nv_bfloat162*)p);
}

// ---------------------------------------------------------------------------
// pf: LN + 1x1 expand (128 -> 256), bf16 mma m16n8k16, 512 threads, cp.async.
// ---------------------------------------------------------------------------
#define PXF 132
__global__ __launch_bounds__(512, 1)
void pf_kernel(const float* __restrict__ in,
               const float* __restrict__ lnw, const float* __restrict__ lnb,
               const float* __restrict__ w, const float* __restrict__ bias,
               __nv_bfloat16* __restrict__ out, int ntiles)
{
  extern __shared__ char smc[];
  __nv_bfloat16* Ws = (__nv_bfloat16*)smc;          // 128 x 136 bf16
  float* Xb0 = (float*)(smc + 34816);               // 128 x 132 f32
  float* Xb1 = (float*)(smc + 34816 + 67584);
  float* sLNw  = (float*)(smc + 169984);
  float* sLNb  = (float*)(smc + 170496);
  float* sMu   = (float*)(smc + 171008);
  float* sRs   = (float*)(smc + 171520);
  float* sPart = (float*)(smc + 172032);            // 1024 f32
  const uint32_t xu0 = smem_u32(smc) + 34816, xu1 = xu0 + 67584;

  const int tid = threadIdx.x;
  const int wid = tid >> 5, lid = tid & 31;
  const int b   = blockIdx.y;
  const int mt  = blockIdx.z;

  const float* wp = w + (size_t)mt*128*128;
  for (int i = tid; i < 128*32; i += 512){
    int oc = i >> 5, c4 = (i & 31) << 2;
    float4 v = *(const float4*)(wp + oc*128 + c4);
    uint32_t* d = (uint32_t*)(Ws + oc*136 + c4);
    d[0] = pkbf(v.x, v.y); d[1] = pkbf(v.z, v.w);
  }
  if (tid < 128){ sLNw[tid] = lnw[tid]; sLNb[tid] = lnb[tid]; }

  const int wm = wid & 7, wn = wid >> 3;
  const int oc0 = wm*16, pxw = wn*64;
  const int r = lid >> 2, cq = lid & 3;
  const int oA = oc0 + r, oB = oc0 + r + 8;
  const float bzA = bias[mt*128 + oA], bzB = bias[mt*128 + oB];

  auto stage = [&](int t){
    const int px0 = (blockIdx.x * ntiles + t) * 128;
    const uint32_t xb = (t & 1) ? xu1 : xu0;
    const float* ipx = in + (size_t)b*(128LL*HW) + px0;
    #pragma unroll 4
    for (int i = tid; i < 128*32; i += 512){
      int ic = i >> 5, pc = (i & 31) << 2;
      cp16(xb + (uint32_t)(ic*PXF + pc)*4u, ipx + (size_t)ic*HW + pc);
    }
    cp_commit();
  };
  stage(0);

  for (int t = 0; t < ntiles; t++){
    if (t+1 < ntiles){ stage(t+1); cp_wait1(); }
    else             { cp_wait0(); }
    __syncthreads();
    float* Xs = (t & 1) ? Xb1 : Xb0;
    const int px0 = (blockIdx.x * ntiles + t) * 128;

    // LN stats
    {
      const int px = tid & 127, q = tid >> 7;
      float s = 0.f, s2 = 0.f;
      #pragma unroll 8
      for (int ic = 0; ic < 32; ic++){
        float v = Xs[(q*32 + ic)*PXF + px]; s += v; s2 += v*v;
      }
      sPart[tid] = s; sPart[512 + tid] = s2;
    }
    __syncthreads();
    if (tid < 128){
      float ss = sPart[tid] + sPart[tid+128] + sPart[tid+256] + sPart[tid+384];
      float qq = sPart[512+tid] + sPart[640+tid] + sPart[768+tid] + sPart[896+tid];
      float mu = ss * (1.f/128.f);
      sMu[tid] = mu;
      sRs[tid] = rsqrtf(qq*(1.f/128.f) - mu*mu + 1e-6f);
    }
    __syncthreads();

    float muv[8], rsv[8];
    #pragma unroll
    for (int ni = 0; ni < 8; ni++){
      int px = pxw + ni*8 + r;
      muv[ni] = sMu[px]; rsv[ni] = sRs[px];
    }

    float acc[8][4];
    #pragma unroll
    for (int ni = 0; ni < 8; ni++)
      #pragma unroll
      for (int j = 0; j < 4; j++) acc[ni][j] = 0.f;

    #pragma unroll
    for (int ks = 0; ks < 8; ks++){
      const int k0 = ks * 16;
      const int kb = k0 + 2*cq;
      uint32_t af[4];
      {
        const __nv_bfloat16* ab = Ws + (oc0 + r)*136 + kb;
        af[0] = *(const uint32_t*)(ab);
        af[1] = *(const uint32_t*)(ab + 8*136);
        af[2] = *(const uint32_t*)(ab + 8);
        af[3] = *(const uint32_t*)(ab + 8*136 + 8);
      }
      const float w0 = sLNw[kb],   b0 = sLNb[kb];
      const float w1 = sLNw[kb+1], b1 = sLNb[kb+1];
      const float w8 = sLNw[kb+8], b8 = sLNb[kb+8];
      const float w9 = sLNw[kb+9], b9 = sLNb[kb+9];
      uint32_t bfr[8][2];
      #pragma unroll
      for (int ni = 0; ni < 8; ni++){
        const float* col = Xs + pxw + ni*8 + r;
        const float mu = muv[ni], rs = rsv[ni];
        float x0 = (col[(kb+0)*PXF] - mu) * (w0*rs) + b0;
        float x1 = (col[(kb+1)*PXF] - mu) * (w1*rs) + b1;
        float x8 = (col[(kb+8)*PXF] - mu) * (w8*rs) + b8;
        float x9 = (col[(kb+9)*PXF] - mu) * (w9*rs) + b9;
        bfr[ni][0] = pkbf(x0, x1);
        bfr[ni][1] = pkbf(x8, x9);
      }
      #pragma unroll
      for (int ni = 0; ni < 8; ni++)
        mma_bf16(acc[ni], af, bfr[ni]);
    }

    __nv_bfloat16* opA = out + ((size_t)b*256 + mt*128 + oA)*HW + px0 + pxw + cq*2;
    __nv_bfloat16* opB = out + ((size_t)b*256 + mt*128 + oB)*HW + px0 + pxw + cq*2;
    #pragma unroll
    for (int ni = 0; ni < 8; ni++){
      *(uint32_t*)(opA + ni*8) = pkbf(acc[ni][0] + bzA, acc[ni][1] + bzA);
      *(uint32_t*)(opB + ni*8) = pkbf(acc[ni][2] + bzB, acc[ni][3] + bzB);
    }
    __syncthreads();
  }
}

// ---------------------------------------------------------------------------
// fuse2: attn + pl, bf16 mma, 64-px tiles, 512 threads.
//   GEMM1: t = (blockdiag(l3w4,l5w3) @ pre + b1) * gate * xh -> Tt (transposed)
//   GEMM2: out = (pl_w @ t + pl_b) * scale + x               -> gmem f32
// ---------------------------------------------------------------------------
#define PT 72
#define F2_W1   0
#define F2_W2   18432
#define F2_PRE  53248
#define F2_GATE 90112
#define F2_XH   126976
#define F2_T    163840
#define F2_TOT  181248
#define TBUF    18432

__global__ __launch_bounds__(512, 1)
void fuse2_kernel(const __nv_bfloat16* __restrict__ pre,
                  const __nv_bfloat16* __restrict__ gate,
                  const __nv_bfloat16* __restrict__ xh, long long xh_bs,
                  const float* __restrict__ w1A, const float* __restrict__ w1B,
                  const float* __restrict__ b1A, const float* __restrict__ b1B,
                  const float* __restrict__ plw, const float* __restrict__ plb,
                  const float* __restrict__ scal, const float* __restrict__ xres,
                  float* __restrict__ out, int ntiles)
{
  extern __shared__ char smc[];
  __nv_bfloat16* W1s = (__nv_bfloat16*)(smc + F2_W1);    // 128 x 64, pitch 72
  __nv_bfloat16* W2s = (__nv_bfloat16*)(smc + F2_W2);    // 128 x 128, pitch 136
  __nv_bfloat16* Tt  = (__nv_bfloat16*)(smc + F2_T);     // 64 px x 128 ch, pitch 136
  const uint32_t sbase = smem_u32(smc);

  const int tid = threadIdx.x;
  const int wid = tid >> 5, lid = tid & 31;
  const int b   = blockIdx.y;

  for (int i = tid; i < 128*16; i += 512){
    int oc = i >> 4, k4 = (i & 15) << 2;
    float4 v = (oc < 64) ? *(const float4*)(w1A + oc*64 + k4)
                         : *(const float4*)(w1B + (oc-64)*64 + k4);
    uint32_t* d = (uint32_t*)(W1s + oc*PT + k4);
    d[0] = pkbf(v.x, v.y); d[1] = pkbf(v.z, v.w);
  }
  for (int i = tid; i < 128*32; i += 512){
    int oc = i >> 5, c4 = (i & 31) << 2;
    float4 v = *(const float4*)(plw + oc*128 + c4);
    uint32_t* d = (uint32_t*)(W2s + oc*136 + c4);
    d[0] = pkbf(v.x, v.y); d[1] = pkbf(v.z, v.w);
  }

  const int wm = wid & 7, wn = wid >> 3;
  const int oc0 = wm*16, pxw = wn*32;
  const int r = lid >> 2, cq = lid & 3;
  const int oA = oc0 + r, oB = oc0 + r + 8;
  const int koff = (oc0 >= 64) ? 64 : 0;

  const float bz1A = (oA < 64) ? b1A[oA] : b1B[oA-64];
  const float bz1B = (oB < 64) ? b1A[oB] : b1B[oB-64];
  const float bz2A = plb[oA], bz2B = plb[oB];
  const float scA  = scal[oA], scB = scal[oB];

  auto stage = [&](int t){
    const int px0 = (blockIdx.x * ntiles + t) * 64;
    const uint32_t buf = (uint32_t)(t & 1) * TBUF;
    const __nv_bfloat16* p1 = pre  + (size_t)b*(128LL*HW) + px0;
    const __nv_bfloat16* p2 = gate + (size_t)b*(128LL*HW) + px0;
    const __nv_bfloat16* p3 = xh   + (size_t)b*xh_bs      + px0;
    #pragma unroll 2
    for (int i = tid; i < 128*8; i += 512){
      int ic = i >> 3, pc = (i & 7) << 3;
      uint32_t off = (uint32_t)(ic*PT + pc)*2u;
      cp16(sbase + F2_PRE  + buf + off, p1 + (size_t)ic*HW + pc);
      cp16(sbase + F2_GATE + buf + off, p2 + (size_t)ic*HW + pc);
      cp16(sbase + F2_XH   + buf + off, p3 + (size_t)ic*HW + pc);
    }
    cp_commit();
  };
  stage(0);

  for (int t = 0; t < ntiles; t++){
    if (t+1 < ntiles){ stage(t+1); cp_wait1(); }
    else             { cp_wait0(); }
    __syncthreads();
    const int buf = (t & 1);
    const __nv_bfloat16* Ps = (const __nv_bfloat16*)(smc + F2_PRE  + buf*TBUF);
    const __nv_bfloat16* Gs = (const __nv_bfloat16*)(smc + F2_GATE + buf*TBUF);
    const __nv_bfloat16* Hs = (const __nv_bfloat16*)(smc + F2_XH   + buf*TBUF);
    const int px0 = (blockIdx.x * ntiles + t) * 64;

    // ---- GEMM1: K=64 (this warp's diag block), 4 x k16 ----
    float a1[4][4];
    #pragma unroll
    for (int ni = 0; ni < 4; ni++)
      #pragma unroll
      for (int j = 0; j < 4; j++) a1[ni][j] = 0.f;

    #pragma unroll
    for (int ks = 0; ks < 4; ks++){
      const int k0 = ks * 16;
      uint32_t af[4];
      {
        const __nv_bfloat16* ab = W1s + (oc0 + r)*PT + k0 + 2*cq;
        af[0] = *(const uint32_t*)(ab);
        af[1] = *(const uint32_t*)(ab + 8*PT);
        af[2] = *(const uint32_t*)(ab + 8);
        af[3] = *(const uint32_t*)(ab + 8*PT + 8);
      }
      uint32_t bfr[4][2];
      #pragma unroll
      for (int ni = 0; ni < 4; ni++){
        const __nv_bfloat16* bb = Ps + (koff + k0 + 2*cq)*PT + pxw + ni*8 + r;
        bfr[ni][0] = pk2u16(bb, PT);
        bfr[ni][1] = pk2u16(bb + 8*PT, PT);
      }
      #pragma unroll
      for (int ni = 0; ni < 4; ni++)
        mma_bf16(a1[ni], af, bfr[ni]);
    }

    // epilogue1: t = (acc + b1) * gate * xh -> Tt (transposed [px][ch])
    #pragma unroll
    for (int ni = 0; ni < 4; ni++){
      const int pxl = pxw + ni*8 + cq*2;
      float2 gA = ldbf2(Gs + oA*PT + pxl);
      float2 hA = ldbf2(Hs + oA*PT + pxl);
      Tt[(pxl  )*136 + oA] = __float2bfloat16((a1[ni][0] + bz1A)*gA.x*hA.x);
      Tt[(pxl+1)*136 + oA] = __float2bfloat16((a1[ni][1] + bz1A)*gA.y*hA.y);
      float2 gB = ldbf2(Gs + oB*PT + pxl);
      float2 hB = ldbf2(Hs + oB*PT + pxl);
      Tt[(pxl  )*136 + oB] = __float2bfloat16((a1[ni][2] + bz1B)*gB.x*hB.x);
      Tt[(pxl+1)*136 + oB] = __float2bfloat16((a1[ni][3] + bz1B)*gB.y*hB.y);
    }
    __syncthreads();

    // ---- GEMM2: out = plw @ t, K=128, 8 x k16 ----
    float a2[4][4];
    #pragma unroll
    for (int ni = 0; ni < 4; ni++)
      #pragma unroll
      for (int j = 0; j < 4; j++) a2[ni][j] = 0.f;

    #pragma unroll
    for (int ks = 0; ks < 8; ks++){
      const int k0 = ks * 16;
      uint32_t af[4];
      {
        const __nv_bfloat16* ab = W2s + (oc0 + r)*136 + k0 + 2*cq;
        af[0] = *(const uint32_t*)(ab);
        af[1] = *(const uint32_t*)(ab + 8*136);
        af[2] = *(const uint32_t*)(ab + 8);
        af[3] = *(const uint32_t*)(ab + 8*136 + 8);
      }
      uint32_t bfr[4][2];
      #pragma unroll
      for (int ni = 0; ni < 4; ni++){
        const __nv_bfloat16* bb = Tt + (pxw + ni*8 + r)*136 + k0 + 2*cq;
        bfr[ni][0] = *(const uint32_t*)(bb);
        bfr[ni][1] = *(const uint32_t*)(bb + 8);
      }
      #pragma unroll
      for (int ni = 0; ni < 4; ni++)
        mma_bf16(a2[ni], af, bfr[ni]);
    }

    // epilogue2
    {
      const int pc = px0 + pxw + cq*2;
      float* opA = out + ((size_t)b*128 + oA)*HW + pc;
      float* opB = out + ((size_t)b*128 + oB)*HW + pc;
      const float* shA = xres + ((size_t)b*128 + oA)*HW + pc;
      const float* shB = xres + ((size_t)b*128 + oB)*HW + pc;
      #pragma unroll
      for (int ni = 0; ni < 4; ni++){
        float2 sA = *(const float2*)(shA + ni*8);
        float2 sB = *(const float2*)(shB + ni*8);
        *(float2*)(opA + ni*8) = make_float2((a2[ni][0] + bz2A)*scA + sA.x,
                                             (a2[ni][1] + bz2A)*scA + sA.y);
        *(float2*)(opB + ni*8) = make_float2((a2[ni][2] + bz2B)*scB + sB.x,
                                             (a2[ni][3] + bz2B)*scB + sB.y);
      }
    }
    __syncthreads();
  }
}

// ---------------------------------------------------------------------------
// branch-1: 32x64 tile. sU1/sT2 in bf16 (pair reads), sIN/sT1 f32 (scalar).
// ---------------------------------------------------------------------------
__global__ __launch_bounds__(256)
void branch1_kernel(const __nv_bfloat16* __restrict__ in, long long in_bs,
    const float* __restrict__ l3w1, const float* __restrict__ l3b1,
    const float* __restrict__ l3w2, const float* __restrict__ l3b2,
    const float* __restrict__ l3w3, const float* __restrict__ l3b3,
    const float* __restrict__ x3aw, const float* __restrict__ x3ab,
    const float* __restrict__ x3bw, const float* __restrict__ x3bb,
    __nv_bfloat16* __restrict__ l3pre, __nv_bfloat16* __restrict__ x3out,
    long long out_bs)
{
  __shared__ float sIN[42*75];
  __shared__ float sT1[42*73];
  __shared__ __nv_bfloat16 sU1[34*66];
  __shared__ __nv_bfloat16 sT2[40*74];
  __shared__ float wsh[42];

  const int c = blockIdx.z & 63, b = blockIdx.z >> 6;
  const int ty0 = blockIdx.y * 32, tx0 = blockIdx.x * 64;
  const int tid = threadIdx.x;

  if (tid < 42){
    float v;
    if      (tid < 3)  v = l3w1[c*3 + tid];
    else if (tid < 6)  v = l3w2[c*3 + tid-3];
    else if (tid < 31) v = l3w3[c*25 + tid-6];
    else if (tid < 34) v = x3aw[c*3 + tid-31];
    else if (tid < 37) v = x3bw[c*3 + tid-34];
    else if (tid == 37) v = l3b1[c];
    else if (tid == 38) v = l3b2[c];
    else if (tid == 39) v = l3b3[c];
    else if (tid == 40) v = x3ab[c];
    else                v = x3bb[c];
    wsh[tid] = v;
  }

  const __nv_bfloat16* ip = in + (long long)b*in_bs + (long long)c*HW;
  for (int i = tid; i < 42*74; i += 256){
    int sy = i / 74, sx = i - sy*74;
    int gy = ty0 + sy - 5, gx = tx0 + sx - 5;
    float v = 0.f;
    if ((unsigned)gy < 128u && (unsigned)gx < 128u) v = __bfloat162float(ip[gy*Wdim + gx]);
    sIN[sy*75 + sx] = v;
  }
  __syncthreads();

  {
    const float w0 = wsh[0], w1 = wsh[1], w2 = wsh[2], bz = wsh[37];
    for (int i = tid; i < 42*72; i += 256){
      int r = i / 72, x = i - r*72;
      const float* s = sIN + r*75 + x;
      sT1[r*73 + x] = w0*s[0] + w1*s[1] + w2*s[2] + bz;
    }
    const float a0 = wsh[31], a1 = wsh[32], a2 = wsh[33], ab = wsh[40];
    for (int i = tid; i < 34*64; i += 256){
      int r = i >> 6, x = i & 63;
      const float* s = sIN + (r+4)*75 + x + 4;
      sU1[r*66 + x] = __float2bfloat16(a0*s[0] + a1*s[1] + a2*s[2] + ab);
    }
  }
  __syncthreads();

  const int oy  = tid >> 3;
  const int ox0 = (tid & 7) << 3;

  {
    const float w0 = wsh[3], w1 = wsh[4], w2 = wsh[5], bz = wsh[38];
    for (int i = tid; i < 40*72; i += 256){
      int r = i / 72, x = i - r*72;
      sT2[r*74 + x] = __float2bfloat16(w0*sT1[r*73+x] + w1*sT1[(r+1)*73+x]
                                       + w2*sT1[(r+2)*73+x] + bz);
    }
    // x3out: 3x1 over sU1, pair loads
    const float vb = wsh[41];
    float o8[8];
    #pragma unroll
    for (int j = 0; j < 8; j++) o8[j] = vb;
    #pragma unroll
    for (int rr = 0; rr < 3; rr++){
      const float wv = wsh[34 + rr];
      const __nv_bfloat16* row = sU1 + (oy+rr)*66 + ox0;
      #pragma unroll
      for (int p = 0; p < 4; p++){
        float2 u = ldbf2(row + 2*p);
        o8[2*p]   += wv*u.x;
        o8[2*p+1] += wv*u.y;
      }
    }
    uint4 u;
    u.x = pkbf(o8[0], o8[1]); u.y = pkbf(o8[2], o8[3]);
    u.z = pkbf(o8[4], o8[5]); u.w = pkbf(o8[6], o8[7]);
    *(uint4*)(x3out + (long long)b*out_bs + (long long)c*HW
              + (long long)(ty0+oy)*Wdim + tx0 + ox0) = u;
  }
  __syncthreads();

  {
    const float bz = wsh[39];
    float a[8];
    #pragma unroll
    for (int j = 0; j < 8; j++) a[j] = bz;
    #pragma unroll
    for (int ky = 0; ky < 5; ky++){
      const __nv_bfloat16* row = sT2 + (oy + 2*ky)*74 + ox0;
      float buf[16];
      #pragma unroll
      for (int p = 0; p < 8; p++){
        float2 u = ldbf2(row + 2*p);
        buf[2*p] = u.x; buf[2*p+1] = u.y;
      }
      #pragma unroll
      for (int kx = 0; kx < 5; kx++){
        const float wv = wsh[6 + ky*5 + kx];
        #pragma unroll
        for (int j = 0; j < 8; j++) a[j] += wv * buf[kx*2 + j];
      }
    }
    uint4 u;
    u.x = pkbf(a[0], a[1]); u.y = pkbf(a[2], a[3]);
    u.z = pkbf(a[4], a[5]); u.w = pkbf(a[6], a[7]);
    *(uint4*)(l3pre + (long long)b*out_bs + (long long)c*HW
              + (long long)(ty0+oy)*Wdim + tx0 + ox0) = u;
  }
}

// ---------------------------------------------------------------------------
// branch-2: 32x64 tile. sIN/sV1 in bf16 (pair reads everywhere).
// ---------------------------------------------------------------------------
__global__ __launch_bounds__(256)
void branch2_kernel(const __nv_bfloat16* __restrict__ in, long long in_bs,
    const float* __restrict__ l5w1, const float* __restrict__ l5b1,
    const float* __restrict__ l5w2, const float* __restrict__ l5b2,
    const float* __restrict__ x5w,  const float* __restrict__ x5b,
    __nv_bfloat16* __restrict__ l5pre, __nv_bfloat16* __restrict__ x5out,
    long long out_bs)
{
  __shared__ __nv_bfloat16 sIN[48*82];
  __shared__ __nv_bfloat16 sV1[44*78];
  __shared__ float wsh[104];

  const int c = blockIdx.z & 63, b = blockIdx.z >> 6;
  const int ty0 = blockIdx.y * 32, tx0 = blockIdx.x * 64;
  const int tid = threadIdx.x;

  if (tid < 102){
    float v;
    if      (tid < 25) v = l5w1[c*25 + tid];
    else if (tid < 74) v = l5w2[c*49 + tid-25];
    else if (tid < 99) v = x5w[c*25 + tid-74];
    else if (tid == 99)  v = l5b1[c];
    else if (tid == 100) v = l5b2[c];
    else                 v = x5b[c];
    wsh[tid] = v;
  }

  const __nv_bfloat16* ip = in + (long long)b*in_bs + (long long)c*HW;
  const __nv_bfloat16 zb = __float2bfloat16(0.f);
  for (int i = tid; i < 48*80; i += 256){
    int sy = i / 80, sx = i - sy*80;
    int gy = ty0 + sy - 8, gx = tx0 + sx - 8;
    __nv_bfloat16 v = zb;
    if ((unsigned)gy < 128u && (unsigned)gx < 128u) v = ip[gy*Wdim + gx];
    sIN[sy*82 + sx] = v;
  }
  __syncthreads();

  const int oy  = tid >> 3;
  const int ox0 = (tid & 7) << 3;

  {
    const float bz = wsh[99];
    for (int g = tid; g < 44*19; g += 256){
      int r = g / 19, c4 = (g - r*19) << 2;
      float a0 = bz, a1 = bz, a2 = bz, a3 = bz;
      #pragma unroll
      for (int ky = 0; ky < 5; ky++){
        const __nv_bfloat16* row = sIN + (r+ky)*82 + c4;
        float buf[8];
        #pragma unroll
        for (int p = 0; p < 4; p++){
          float2 u = ldbf2(row + 2*p);
          buf[2*p] = u.x; buf[2*p+1] = u.y;
        }
        #pragma unroll
        for (int kx = 0; kx < 5; kx++){
          const float wv = wsh[ky*5+kx];
          a0 += wv*buf[kx+0];
          a1 += wv*buf[kx+1];
          a2 += wv*buf[kx+2];
          a3 += wv*buf[kx+3];
        }
      }
      uint32_t* d = (uint32_t*)(sV1 + r*78 + c4);
      d[0] = pkbf(a0, a1); d[1] = pkbf(a2, a3);
    }
    // gate x5out
    const float xb = wsh[101];
    float a[8];
    #pragma unroll
    for (int j = 0; j < 8; j++) a[j] = xb;
    #pragma unroll
    for (int ky = 0; ky < 5; ky++){
      const __nv_bfloat16* row = sIN + (oy+6+ky)*82 + ox0 + 6;
      float buf[12];
      #pragma unroll
      for (int p = 0; p < 6; p++){
        float2 u = ldbf2(row + 2*p);
        buf[2*p] = u.x; buf[2*p+1] = u.y;
      }
      #pragma unroll
      for (int kx = 0; kx < 5; kx++){
        const float wv = wsh[74 + ky*5 + kx];
        #pragma unroll
        for (int j = 0; j < 8; j++) a[j] += wv * buf[kx + j];
      }
    }
    uint4 u;
    u.x = pkbf(a[0], a[1]); u.y = pkbf(a[2], a[3]);
    u.z = pkbf(a[4], a[5]); u.w = pkbf(a[6], a[7]);
    *(uint4*)(x5out + (long long)b*out_bs + (long long)c*HW
              + (long long)(ty0+oy)*Wdim + tx0 + ox0) = u;
  }
  __syncthreads();

  {
    const float bz = wsh[100];
    float a[8];
    #pragma unroll
    for (int j = 0; j < 8; j++) a[j] = bz;
    #pragma unroll
    for (int ky = 0; ky < 7; ky++){
      const __nv_bfloat16* row = sV1 + (oy + 2*ky)*78 + ox0;
      float buf[20];
      #pragma unroll
      for (int p = 0; p < 10; p++){
        float2 u = ldbf2(row + 2*p);
        buf[2*p] = u.x; buf[2*p+1] = u.y;
      }
      #pragma unroll
      for (int kx = 0; kx < 7; kx++){
        const float wv = wsh[25 + ky*7 + kx];
        #pragma unroll
        for (int j = 0; j < 8; j++) a[j] += wv * buf[kx*2 + j];
      }
    }
    uint4 u;
    u.x = pkbf(a[0], a[1]); u.y = pkbf(a[2], a[3]);
    u.z = pkbf(a[4], a[5]); u.w = pkbf(a[6], a[7]);
    *(uint4*)(l5pre + (long long)b*out_bs + (long long)c*HW
              + (long long)(ty0+oy)*Wdim + tx0 + ox0) = u;
  }
}

// ---------------------------------------------------------------------------
extern "C" void kernel_launch(void* const* d_in, const int* in_sizes, int n_in,
                              void* d_out, int out_size)
{
  const float* x    = (const float*)d_in[0];
  const float* ln_w = (const float*)d_in[1];
  const float* ln_b = (const float*)d_in[2];
  const float* scale= (const float*)d_in[3];
  const float* pf_w = (const float*)d_in[4];
  const float* pf_b = (const float*)d_in[5];
  const float* l3w1 = (const float*)d_in[6];
  const float* l3b1 = (const float*)d_in[7];
  const float* l3w2 = (const float*)d_in[8];
  const float* l3b2 = (const float*)d_in[9];
  const float* l3w3 = (const float*)d_in[10];
  const float* l3b3 = (const float*)d_in[11];
  const float* l3w4 = (const float*)d_in[12];
  const float* l3b4 = (const float*)d_in[13];
  const float* l5w1 = (const float*)d_in[14];
  const float* l5b1 = (const float*)d_in[15];
  const float* l5w2 = (const float*)d_in[16];
  const float* l5b2 = (const float*)d_in[17];
  const float* l5w3 = (const float*)d_in[18];
  const float* l5b3 = (const float*)d_in[19];
  const float* x3aw = (const float*)d_in[20];
  const float* x3ab = (const float*)d_in[21];
  const float* x3bw = (const float*)d_in[22];
  const float* x3bb = (const float*)d_in[23];
  const float* x5w  = (const float*)d_in[24];
  const float* x5b  = (const float*)d_in[25];
  const float* pl_w = (const float*)d_in[26];
  const float* pl_b = (const float*)d_in[27];
  float* out = (float*)d_out;

  __nv_bfloat16 *p_h, *p_t1, *p_x3;
  cudaGetSymbolAddress((void**)&p_h,  g_h);
  cudaGetSymbolAddress((void**)&p_t1, g_t1);
  cudaGetSymbolAddress((void**)&p_x3, g_x3);

  const long long BS_H = 256LL*HW, BS128 = 128LL*HW;
  dim3 gbr(2, 4, 16*64);

  // 1) LN + pf expand (128 -> 256)
  {
    const int SM_PF = 176128;
    cudaFuncSetAttribute((const void*)pf_kernel, cudaFuncAttributeMaxDynamicSharedMemorySize, SM_PF);
    pf_kernel<<<dim3(32,16,2),512,SM_PF>>>(x, ln_w, ln_b, pf_w, pf_b, p_h, 4);
  }
  // 2) fused dw branches
  branch1_kernel<<<gbr,256>>>(p_h, BS_H, l3w1,l3b1, l3w2,l3b2, l3w3,l3b3,
                              x3aw,x3ab, x3bw,x3bb, p_t1, p_x3, BS128);
  branch2_kernel<<<gbr,256>>>(p_h + 64LL*HW, BS_H, l5w1,l5b1, l5w2,l5b2,
                              x5w,x5b, p_t1 + 64LL*HW, p_x3 + 64LL*HW, BS128);
  // 3+4) fused attn+pl
  {
    cudaFuncSetAttribute((const void*)fuse2_kernel, cudaFuncAttributeMaxDynamicSharedMemorySize, F2_TOT);
    fuse2_kernel<<<dim3(64,16),512,F2_TOT>>>(p_t1, p_x3, p_h + 128LL*HW, BS_H,
                                             l3w4, l5w3, l3b4, l5b3,
                                             pl_w, pl_b, scale, x, out, 4);
  }
}